// round 1
// baseline (speedup 1.0000x reference)
#include <cuda_runtime.h>

// ---------------------------------------------------------------------------
// GraphSAGE (LSTM aggregator) — 2 layers, N=100000, K=16, D=128
//
// Decomposition per layer:
//   1. proj:     xproj[N,512] = x @ Wih^T + (bih + bhh)         (one GEMM)
//   2. lstm:     persistent per-block LSTM over K=16 steps; step t gathers
//                xproj[nbr[:,t]] and adds h @ Whh^T (f32x2 FMA microkernel)
//   3. outproj:  y = x @ Wself^T + bself + h_neigh @ Wneigh^T   (+ BN partials)
//   4. bn_reduce + bn_apply (+ReLU for layer 1)
// ---------------------------------------------------------------------------

#define N_NODES 100000
#define KNBR    16
#define D       128
#define D4      512
#define GM      782      // ceil(N_NODES / 128)

// scratch (static device allocations — no cudaMalloc allowed)
__device__ float g_xproj [(size_t)N_NODES * D4];   // 204.8 MB
__device__ float g_hneigh[(size_t)N_NODES * D];
__device__ float g_tmp   [(size_t)N_NODES * D];
__device__ float g_y1    [(size_t)N_NODES * D];
__device__ float g_psum  [GM * D];
__device__ float g_psq   [GM * D];
__device__ float g_stats [2 * D];                  // mean[128], rstd[128]

// ---------------------------------------------------------------------------
// f32x2 packed-FMA helpers (B300 sm_103a; only reachable via inline PTX)
// ---------------------------------------------------------------------------
__device__ __forceinline__ void fma2(unsigned long long &d,
                                     unsigned long long a,
                                     unsigned long long b) {
    asm("fma.rn.f32x2 %0, %1, %2, %0;" : "+l"(d) : "l"(a), "l"(b));
}
__device__ __forceinline__ unsigned long long pack2(float x) {
    unsigned int xi = __float_as_uint(x);
    unsigned long long r;
    asm("mov.b64 %0, {%1, %1};" : "=l"(r) : "r"(xi));
    return r;
}
__device__ __forceinline__ float2 unpack2(unsigned long long v) {
    unsigned int lo, hi;
    asm("mov.b64 {%0, %1}, %2;" : "=r"(lo), "=r"(hi) : "l"(v));
    return make_float2(__uint_as_float(lo), __uint_as_float(hi));
}

__device__ __forceinline__ float sigf(float x) {
    return __fdividef(1.0f, 1.0f + __expf(-x));
}
__device__ __forceinline__ float tanh_f(float x) {
    return 2.0f * __fdividef(1.0f, 1.0f + __expf(-2.0f * x)) - 1.0f;
}

// ---------------------------------------------------------------------------
// Kernel 1: xproj = A[M,128] @ W[512,128]^T + (b1 + b2)   -> C[M,512]
// 128x128 output tile per block, 256 threads, 8x8 micro-tile.
// ---------------------------------------------------------------------------
__global__ __launch_bounds__(256) void proj_kernel(
    const float* __restrict__ A, const float* __restrict__ W,
    const float* __restrict__ b1, const float* __restrict__ b2,
    float* __restrict__ C)
{
    __shared__ float As[16 * 128];
    __shared__ float Bs[16 * 128];
    const int tid = threadIdx.x;
    const int tx = tid & 15, ty = tid >> 4;
    const int m0 = blockIdx.x * 128;
    const int n0 = blockIdx.y * 128;

    float acc[8][8];
#pragma unroll
    for (int i = 0; i < 8; i++)
#pragma unroll
        for (int j = 0; j < 8; j++) acc[i][j] = 0.f;

#pragma unroll 1
    for (int kc = 0; kc < 128; kc += 16) {
        __syncthreads();
#pragma unroll
        for (int q = 0; q < 2; q++) {
            int slot = tid * 2 + q;          // 0..511
            int row  = slot >> 2;            // 0..127
            int k4   = (slot & 3) << 2;      // 0,4,8,12
            float4 va = make_float4(0.f, 0.f, 0.f, 0.f);
            int gm = m0 + row;
            if (gm < N_NODES) va = *(const float4*)(A + (size_t)gm * 128 + kc + k4);
            As[(k4 + 0) * 128 + row] = va.x;
            As[(k4 + 1) * 128 + row] = va.y;
            As[(k4 + 2) * 128 + row] = va.z;
            As[(k4 + 3) * 128 + row] = va.w;
            float4 vb = *(const float4*)(W + (size_t)(n0 + row) * 128 + kc + k4);
            Bs[(k4 + 0) * 128 + row] = vb.x;
            Bs[(k4 + 1) * 128 + row] = vb.y;
            Bs[(k4 + 2) * 128 + row] = vb.z;
            Bs[(k4 + 3) * 128 + row] = vb.w;
        }
        __syncthreads();
#pragma unroll
        for (int k = 0; k < 16; k++) {
            float a[8], b[8];
            *(float4*)&a[0] = *(const float4*)&As[k * 128 + tx * 8];
            *(float4*)&a[4] = *(const float4*)&As[k * 128 + tx * 8 + 4];
            *(float4*)&b[0] = *(const float4*)&Bs[k * 128 + ty * 8];
            *(float4*)&b[4] = *(const float4*)&Bs[k * 128 + ty * 8 + 4];
#pragma unroll
            for (int i = 0; i < 8; i++)
#pragma unroll
                for (int j = 0; j < 8; j++)
                    acc[i][j] = fmaf(a[i], b[j], acc[i][j]);
        }
    }

    float bias[8];
#pragma unroll
    for (int j = 0; j < 8; j++) {
        int n = n0 + ty * 8 + j;
        bias[j] = b1[n] + b2[n];
    }
#pragma unroll
    for (int i = 0; i < 8; i++) {
        int gm = m0 + tx * 8 + i;
        if (gm >= N_NODES) continue;
#pragma unroll
        for (int j4 = 0; j4 < 8; j4 += 4) {
            float4 o;
            o.x = acc[i][j4 + 0] + bias[j4 + 0];
            o.y = acc[i][j4 + 1] + bias[j4 + 1];
            o.z = acc[i][j4 + 2] + bias[j4 + 2];
            o.w = acc[i][j4 + 3] + bias[j4 + 3];
            *(float4*)(C + (size_t)gm * 512 + n0 + ty * 8 + j4) = o;
        }
    }
}

// ---------------------------------------------------------------------------
// Kernel 2: persistent LSTM aggregation.
// Block = 32 nodes, 256 threads. Warp w owns nodes {w, w+8, w+16, w+24};
// lane td owns d = td*4 .. td*4+3. h lives in SMEM, c in registers.
// Per step: acc = gather(xproj[idx]) ; acc += h @ Whh^T (k-major SMEM chunks,
// f32x2 FMAs); gates; write new h.
// ---------------------------------------------------------------------------
__global__ __launch_bounds__(256, 2) void lstm_kernel(
    const float* __restrict__ xproj,   // [N,512] (biases folded in)
    const int*   __restrict__ nbr,     // [N,16]
    const float* __restrict__ Whh,     // [512,128]
    float*       __restrict__ hout)    // [N,128]
{
    __shared__ float Ws[16 * 512];     // k-major chunk of Whh   (32 KB)
    __shared__ float hs[32 * 128];     // hidden state           (16 KB)
    __shared__ int   nbs[32 * KNBR];   // neighbor ids           ( 2 KB)

    const int tid = threadIdx.x;
    const int tn  = tid >> 5;          // warp id 0..7
    const int td  = tid & 31;          // lane
    const int d4  = td * 4;
    const int base = blockIdx.x * 32;

    for (int i = tid; i < 32 * KNBR; i += 256) nbs[i] = nbr[(size_t)base * KNBR + i];
    __syncthreads();

    unsigned long long accx[4][4], accy[4][4];  // [node j][gate g], d-pairs
    float c_r[4][4];
#pragma unroll
    for (int j = 0; j < 4; j++)
#pragma unroll
        for (int e = 0; e < 4; e++) c_r[j][e] = 0.f;

#pragma unroll 1
    for (int t = 0; t < KNBR; t++) {
        // init acc from gathered projection (includes both biases)
#pragma unroll
        for (int j = 0; j < 4; j++) {
            int n   = tn + 8 * j;
            int idx = nbs[n * KNBR + t];
            const ulonglong2* gp = (const ulonglong2*)(xproj + (size_t)idx * 512 + d4);
#pragma unroll
            for (int g = 0; g < 4; g++) {
                ulonglong2 v = gp[g * 32];      // +g*128 floats
                accx[j][g] = v.x;
                accy[j][g] = v.y;
            }
        }

        if (t > 0) {
#pragma unroll 1
            for (int kc = 0; kc < 128; kc += 16) {
                __syncthreads();
                // stage Whh rows [0,512) x k[kc,kc+16) transposed to k-major
#pragma unroll
                for (int rr = 0; rr < 2; rr++) {
                    int r = tid + rr * 256;
                    const float4* wp = (const float4*)(Whh + (size_t)r * 128 + kc);
#pragma unroll
                    for (int q = 0; q < 4; q++) {
                        float4 v = wp[q];
                        Ws[(q * 4 + 0) * 512 + r] = v.x;
                        Ws[(q * 4 + 1) * 512 + r] = v.y;
                        Ws[(q * 4 + 2) * 512 + r] = v.z;
                        Ws[(q * 4 + 3) * 512 + r] = v.w;
                    }
                }
                __syncthreads();
#pragma unroll 4
                for (int k = 0; k < 16; k++) {
                    ulonglong2 w[4];
#pragma unroll
                    for (int g = 0; g < 4; g++)
                        w[g] = *(const ulonglong2*)&Ws[k * 512 + g * 128 + d4];
#pragma unroll
                    for (int j = 0; j < 4; j++) {
                        unsigned long long hh = pack2(hs[(tn + 8 * j) * 128 + kc + k]);
#pragma unroll
                        for (int g = 0; g < 4; g++) {
                            fma2(accx[j][g], hh, w[g].x);
                            fma2(accy[j][g], hh, w[g].y);
                        }
                    }
                }
            }
        }

        __syncthreads();   // all reads of hs finished before overwrite
        // gate nonlinearities + state update
#pragma unroll
        for (int j = 0; j < 4; j++) {
            float zi[4], zf[4], zg[4], zo[4];
            { float2 a = unpack2(accx[j][0]), b = unpack2(accy[j][0]);
              zi[0]=a.x; zi[1]=a.y; zi[2]=b.x; zi[3]=b.y; }
            { float2 a = unpack2(accx[j][1]), b = unpack2(accy[j][1]);
              zf[0]=a.x; zf[1]=a.y; zf[2]=b.x; zf[3]=b.y; }
            { float2 a = unpack2(accx[j][2]), b = unpack2(accy[j][2]);
              zg[0]=a.x; zg[1]=a.y; zg[2]=b.x; zg[3]=b.y; }
            { float2 a = unpack2(accx[j][3]), b = unpack2(accy[j][3]);
              zo[0]=a.x; zo[1]=a.y; zo[2]=b.x; zo[3]=b.y; }
            float hv[4];
#pragma unroll
            for (int e = 0; e < 4; e++) {
                float i_ = sigf(zi[e]);
                float f_ = sigf(zf[e]);
                float g_ = tanh_f(zg[e]);
                float o_ = sigf(zo[e]);
                float c  = f_ * c_r[j][e] + i_ * g_;
                c_r[j][e] = c;
                hv[e] = o_ * tanh_f(c);
            }
            *(float4*)&hs[(tn + 8 * j) * 128 + d4] =
                make_float4(hv[0], hv[1], hv[2], hv[3]);
        }
        __syncthreads();
    }

    // write final hidden state
#pragma unroll
    for (int j = 0; j < 4; j++) {
        int n = base + tn + 8 * j;
        *(float4*)(hout + (size_t)n * 128 + d4) =
            *(const float4*)&hs[(tn + 8 * j) * 128 + d4];
    }
}

// ---------------------------------------------------------------------------
// Kernel 3: y = X @ Wself^T + bself + Hn @ Wneigh^T; also emits per-block
// column sum / sumsq partials for BatchNorm.
// ---------------------------------------------------------------------------
__global__ __launch_bounds__(256) void outproj_kernel(
    const float* __restrict__ X,  const float* __restrict__ Wself,
    const float* __restrict__ bself,
    const float* __restrict__ Hn, const float* __restrict__ Wneigh,
    float* __restrict__ Y, float* __restrict__ psum, float* __restrict__ psq)
{
    __shared__ float As[16 * 128];
    __shared__ float Bs[16 * 128];
    const int tid = threadIdx.x;
    const int tx = tid & 15, ty = tid >> 4;
    const int m0 = blockIdx.x * 128;

    float acc[8][8];
#pragma unroll
    for (int i = 0; i < 8; i++)
#pragma unroll
        for (int j = 0; j < 8; j++) acc[i][j] = 0.f;

#pragma unroll 1
    for (int seg = 0; seg < 2; seg++) {
        const float* Ap = seg ? Hn : X;
        const float* Wp = seg ? Wneigh : Wself;
#pragma unroll 1
        for (int kc = 0; kc < 128; kc += 16) {
            __syncthreads();
#pragma unroll
            for (int q = 0; q < 2; q++) {
                int slot = tid * 2 + q;
                int row  = slot >> 2;
                int k4   = (slot & 3) << 2;
                float4 va = make_float4(0.f, 0.f, 0.f, 0.f);
                int gm = m0 + row;
                if (gm < N_NODES) va = *(const float4*)(Ap + (size_t)gm * 128 + kc + k4);
                As[(k4 + 0) * 128 + row] = va.x;
                As[(k4 + 1) * 128 + row] = va.y;
                As[(k4 + 2) * 128 + row] = va.z;
                As[(k4 + 3) * 128 + row] = va.w;
                float4 vb = *(const float4*)(Wp + (size_t)row * 128 + kc + k4);
                Bs[(k4 + 0) * 128 + row] = vb.x;
                Bs[(k4 + 1) * 128 + row] = vb.y;
                Bs[(k4 + 2) * 128 + row] = vb.z;
                Bs[(k4 + 3) * 128 + row] = vb.w;
            }
            __syncthreads();
#pragma unroll
            for (int k = 0; k < 16; k++) {
                float a[8], b[8];
                *(float4*)&a[0] = *(const float4*)&As[k * 128 + tx * 8];
                *(float4*)&a[4] = *(const float4*)&As[k * 128 + tx * 8 + 4];
                *(float4*)&b[0] = *(const float4*)&Bs[k * 128 + ty * 8];
                *(float4*)&b[4] = *(const float4*)&Bs[k * 128 + ty * 8 + 4];
#pragma unroll
                for (int i = 0; i < 8; i++)
#pragma unroll
                    for (int j = 0; j < 8; j++)
                        acc[i][j] = fmaf(a[i], b[j], acc[i][j]);
            }
        }
    }

    float bias[8];
#pragma unroll
    for (int j = 0; j < 8; j++) bias[j] = bself[ty * 8 + j];

    float cs[8], cq[8];
#pragma unroll
    for (int j = 0; j < 8; j++) { cs[j] = 0.f; cq[j] = 0.f; }

#pragma unroll
    for (int i = 0; i < 8; i++) {
        int gm = m0 + tx * 8 + i;
        if (gm < N_NODES) {
            float v[8];
#pragma unroll
            for (int j = 0; j < 8; j++) v[j] = acc[i][j] + bias[j];
            *(float4*)(Y + (size_t)gm * 128 + ty * 8 + 0) =
                make_float4(v[0], v[1], v[2], v[3]);
            *(float4*)(Y + (size_t)gm * 128 + ty * 8 + 4) =
                make_float4(v[4], v[5], v[6], v[7]);
#pragma unroll
            for (int j = 0; j < 8; j++) { cs[j] += v[j]; cq[j] += v[j] * v[j]; }
        }
    }

    // cross-thread column reduction via SMEM (reuse As)
    float* red = As;
    __syncthreads();
#pragma unroll
    for (int j = 0; j < 8; j++) red[tx * 128 + ty * 8 + j] = cs[j];
    __syncthreads();
    if (tid < 128) {
        float s = 0.f;
#pragma unroll
        for (int x = 0; x < 16; x++) s += red[x * 128 + tid];
        psum[blockIdx.x * 128 + tid] = s;
    }
    __syncthreads();
#pragma unroll
    for (int j = 0; j < 8; j++) red[tx * 128 + ty * 8 + j] = cq[j];
    __syncthreads();
    if (tid < 128) {
        float s = 0.f;
#pragma unroll
        for (int x = 0; x < 16; x++) s += red[x * 128 + tid];
        psq[blockIdx.x * 128 + tid] = s;
    }
}

// ---------------------------------------------------------------------------
// Kernel 4: final BN statistics
// ---------------------------------------------------------------------------
__global__ void bn_reduce(const float* __restrict__ psum,
                          const float* __restrict__ psq,
                          float* __restrict__ stats)
{
    int c = threadIdx.x;   // 0..127
    float s = 0.f, s2 = 0.f;
    for (int b = 0; b < GM; b++) {
        s  += psum[b * 128 + c];
        s2 += psq [b * 128 + c];
    }
    float mean = s / (float)N_NODES;
    float var  = s2 / (float)N_NODES - mean * mean;
    if (var < 0.f) var = 0.f;
    stats[c]       = mean;
    stats[128 + c] = rsqrtf(var + 1e-5f);
}

// ---------------------------------------------------------------------------
// Kernel 5: BN apply (+ optional ReLU)
// ---------------------------------------------------------------------------
__global__ void bn_apply(const float* __restrict__ X,
                         const float* __restrict__ stats,
                         const float* __restrict__ gamma,
                         const float* __restrict__ beta,
                         float* __restrict__ Y, int relu)
{
    size_t i = (size_t)blockIdx.x * blockDim.x + threadIdx.x;   // float4 index
    if (i * 4 >= (size_t)N_NODES * D) return;
    float4 v = ((const float4*)X)[i];
    int c = (int)((i * 4) & (D - 1));
    float r[4] = {v.x, v.y, v.z, v.w};
#pragma unroll
    for (int e = 0; e < 4; e++) {
        float y = (r[e] - stats[c + e]) * stats[128 + c + e] * gamma[c + e] + beta[c + e];
        if (relu) y = fmaxf(y, 0.f);
        r[e] = y;
    }
    ((float4*)Y)[i] = make_float4(r[0], r[1], r[2], r[3]);
}

// ---------------------------------------------------------------------------
// launch
// ---------------------------------------------------------------------------
extern "C" void kernel_launch(void* const* d_in, const int* in_sizes, int n_in,
                              void* d_out, int out_size)
{
    const float* in_feat = (const float*)d_in[0];
    const int*   nbr     = (const int*)  d_in[1];
    const float* Wih1    = (const float*)d_in[2];
    const float* Whh1    = (const float*)d_in[3];
    const float* bih1    = (const float*)d_in[4];
    const float* bhh1    = (const float*)d_in[5];
    const float* Wself1  = (const float*)d_in[6];
    const float* bself1  = (const float*)d_in[7];
    const float* Wneigh1 = (const float*)d_in[8];
    const float* gamma1  = (const float*)d_in[9];
    const float* beta1   = (const float*)d_in[10];
    const float* Wih2    = (const float*)d_in[11];
    const float* Whh2    = (const float*)d_in[12];
    const float* bih2    = (const float*)d_in[13];
    const float* bhh2    = (const float*)d_in[14];
    const float* Wself2  = (const float*)d_in[15];
    const float* bself2  = (const float*)d_in[16];
    const float* Wneigh2 = (const float*)d_in[17];
    const float* gamma2  = (const float*)d_in[18];
    const float* beta2   = (const float*)d_in[19];
    float* out = (float*)d_out;

    float *xp, *hn, *tmp, *y1, *ps, *pq, *st;
    cudaGetSymbolAddress((void**)&xp,  g_xproj);
    cudaGetSymbolAddress((void**)&hn,  g_hneigh);
    cudaGetSymbolAddress((void**)&tmp, g_tmp);
    cudaGetSymbolAddress((void**)&y1,  g_y1);
    cudaGetSymbolAddress((void**)&ps,  g_psum);
    cudaGetSymbolAddress((void**)&pq,  g_psq);
    cudaGetSymbolAddress((void**)&st,  g_stats);

    dim3 gproj(GM, 4);
    int bn_blocks = (int)(((size_t)N_NODES * D / 4 + 255) / 256);

    // ---- layer 1 ----
    proj_kernel   <<<gproj, 256>>>(in_feat, Wih1, bih1, bhh1, xp);
    lstm_kernel   <<<N_NODES / 32, 256>>>(xp, nbr, Whh1, hn);
    outproj_kernel<<<GM, 256>>>(in_feat, Wself1, bself1, hn, Wneigh1, tmp, ps, pq);
    bn_reduce     <<<1, 128>>>(ps, pq, st);
    bn_apply      <<<bn_blocks, 256>>>(tmp, st, gamma1, beta1, y1, 1);

    // ---- layer 2 ----
    proj_kernel   <<<gproj, 256>>>(y1, Wih2, bih2, bhh2, xp);
    lstm_kernel   <<<N_NODES / 32, 256>>>(xp, nbr, Whh2, hn);
    outproj_kernel<<<GM, 256>>>(y1, Wself2, bself2, hn, Wneigh2, tmp, ps, pq);
    bn_reduce     <<<1, 128>>>(ps, pq, st);
    bn_apply      <<<bn_blocks, 256>>>(tmp, st, gamma2, beta2, out, 0);
}

// round 2
// speedup vs baseline: 1.7541x; 1.7541x over previous
#include <cuda_runtime.h>

// ---------------------------------------------------------------------------
// GraphSAGE (LSTM aggregator) — 2 layers, N=100000, K=16, D=128
//
//   1. proj:     xproj[N,512] = x @ Wih^T + (bih + bhh)          (FFMA GEMM)
//   2. lstm:     per-block (64 nodes) LSTM, 16 steps; recurrent h@Whh^T via
//                mma.sync tf32 tensor cores, gather + gates in fp32
//   3. outproj:  y = x @ Wself^T + bself + h_neigh @ Wneigh^T    (+BN partials)
//   4. bn_reduce (parallel) + bn_apply (+ReLU layer 1)
// ---------------------------------------------------------------------------

#define N_NODES 100000
#define KNBR    16
#define D       128
#define D4      512
#define GM      782              // ceil(N_NODES / 128)
#define LBLK    1563             // ceil(N_NODES / 64)

__device__ float g_xproj [(size_t)N_NODES * D4];
__device__ float g_hneigh[(size_t)N_NODES * D];
__device__ float g_tmp   [(size_t)N_NODES * D];
__device__ float g_y1    [(size_t)N_NODES * D];
__device__ float g_psum  [GM * D];
__device__ float g_psq   [GM * D];
__device__ float g_stats [2 * D];

__device__ __forceinline__ float sigf(float x) {
    return __fdividef(1.0f, 1.0f + __expf(-x));
}
__device__ __forceinline__ float tanh_f(float x) {
    return 2.0f * __fdividef(1.0f, 1.0f + __expf(-2.0f * x)) - 1.0f;
}
__device__ __forceinline__ unsigned cvt_tf32(float x) {
    unsigned u;
    asm("cvt.rna.tf32.f32 %0, %1;" : "=r"(u) : "f"(x));
    return u;
}
__device__ __forceinline__ void mma_tf32(float* d, const unsigned* a,
                                         unsigned b0, unsigned b1) {
    asm volatile(
        "mma.sync.aligned.m16n8k8.row.col.f32.tf32.tf32.f32 "
        "{%0,%1,%2,%3}, {%4,%5,%6,%7}, {%8,%9}, {%0,%1,%2,%3};"
        : "+f"(d[0]), "+f"(d[1]), "+f"(d[2]), "+f"(d[3])
        : "r"(a[0]), "r"(a[1]), "r"(a[2]), "r"(a[3]), "r"(b0), "r"(b1));
}

// ---------------------------------------------------------------------------
// Kernel 1: xproj = A[M,128] @ W[512,128]^T + (b1 + b2)   -> C[M,512]
// ---------------------------------------------------------------------------
__global__ __launch_bounds__(256) void proj_kernel(
    const float* __restrict__ A, const float* __restrict__ W,
    const float* __restrict__ b1, const float* __restrict__ b2,
    float* __restrict__ C)
{
    __shared__ float As[16 * 128];
    __shared__ float Bs[16 * 128];
    const int tid = threadIdx.x;
    const int tx = tid & 15, ty = tid >> 4;
    const int m0 = blockIdx.x * 128;
    const int n0 = blockIdx.y * 128;

    float acc[8][8];
#pragma unroll
    for (int i = 0; i < 8; i++)
#pragma unroll
        for (int j = 0; j < 8; j++) acc[i][j] = 0.f;

#pragma unroll 1
    for (int kc = 0; kc < 128; kc += 16) {
        __syncthreads();
#pragma unroll
        for (int q = 0; q < 2; q++) {
            int slot = tid * 2 + q;
            int row  = slot >> 2;
            int k4   = (slot & 3) << 2;
            float4 va = make_float4(0.f, 0.f, 0.f, 0.f);
            int gm = m0 + row;
            if (gm < N_NODES) va = *(const float4*)(A + (size_t)gm * 128 + kc + k4);
            As[(k4 + 0) * 128 + row] = va.x;
            As[(k4 + 1) * 128 + row] = va.y;
            As[(k4 + 2) * 128 + row] = va.z;
            As[(k4 + 3) * 128 + row] = va.w;
            float4 vb = *(const float4*)(W + (size_t)(n0 + row) * 128 + kc + k4);
            Bs[(k4 + 0) * 128 + row] = vb.x;
            Bs[(k4 + 1) * 128 + row] = vb.y;
            Bs[(k4 + 2) * 128 + row] = vb.z;
            Bs[(k4 + 3) * 128 + row] = vb.w;
        }
        __syncthreads();
#pragma unroll
        for (int k = 0; k < 16; k++) {
            float a[8], b[8];
            *(float4*)&a[0] = *(const float4*)&As[k * 128 + tx * 8];
            *(float4*)&a[4] = *(const float4*)&As[k * 128 + tx * 8 + 4];
            *(float4*)&b[0] = *(const float4*)&Bs[k * 128 + ty * 8];
            *(float4*)&b[4] = *(const float4*)&Bs[k * 128 + ty * 8 + 4];
#pragma unroll
            for (int i = 0; i < 8; i++)
#pragma unroll
                for (int j = 0; j < 8; j++)
                    acc[i][j] = fmaf(a[i], b[j], acc[i][j]);
        }
    }

    float bias[8];
#pragma unroll
    for (int j = 0; j < 8; j++) {
        int n = n0 + ty * 8 + j;
        bias[j] = b1[n] + b2[n];
    }
#pragma unroll
    for (int i = 0; i < 8; i++) {
        int gm = m0 + tx * 8 + i;
        if (gm >= N_NODES) continue;
#pragma unroll
        for (int j4 = 0; j4 < 8; j4 += 4) {
            float4 o;
            o.x = acc[i][j4 + 0] + bias[j4 + 0];
            o.y = acc[i][j4 + 1] + bias[j4 + 1];
            o.z = acc[i][j4 + 2] + bias[j4 + 2];
            o.w = acc[i][j4 + 3] + bias[j4 + 3];
            *(float4*)(C + (size_t)gm * 512 + n0 + ty * 8 + j4) = o;
        }
    }
}

// ---------------------------------------------------------------------------
// Kernel 2: LSTM aggregation with tf32 mma.sync.
// Block = 64 nodes, 256 threads (8 warps). Warp w owns, inside EVERY gate
// segment, columns [w*16, w*16+16) -> gate combine is lane-local.
// z accumulators in registers (c-fragment layout), h in SMEM (fp32, padded),
// Whh streamed per 16-k chunk into SMEM (k-major, pre-converted tf32).
// ---------------------------------------------------------------------------
#define HS_STRIDE 132
#define WS_STRIDE 520
#define LSTM_SMEM_BYTES ((64 * HS_STRIDE + 16 * WS_STRIDE + 64 * KNBR) * 4)

__global__ __launch_bounds__(256) void lstm_mma_kernel(
    const float* __restrict__ xproj,   // [N,512] biases folded in
    const int*   __restrict__ nbr,     // [N,16]
    const float* __restrict__ Whh,     // [512,128]
    float*       __restrict__ hout)    // [N,128]
{
    extern __shared__ float sm[];
    float*    hs  = sm;                                  // [64][132]
    unsigned* Ws  = (unsigned*)(sm + 64 * HS_STRIDE);    // [16][520] tf32 bits
    int*      nbs = (int*)(sm + 64 * HS_STRIDE + 16 * WS_STRIDE);

    const int tid  = threadIdx.x;
    const int w    = tid >> 5;
    const int lane = tid & 31;
    const int g4   = lane >> 2;       // group id 0..7
    const int t4   = lane & 3;        // thread-in-group 0..3
    const int base = blockIdx.x * 64;

    for (int i = tid; i < 64 * KNBR; i += 256) {
        int r = i >> 4;
        int nid = base + r;
        if (nid >= N_NODES) nid = N_NODES - 1;
        nbs[i] = nbr[(size_t)nid * KNBR + (i & 15)];
    }
    __syncthreads();

    float d[4][8][4];          // [m-tile][n-tile (gate-interleaved)][frag]
    float c_r[4][2][4];
#pragma unroll
    for (int mt = 0; mt < 4; mt++)
#pragma unroll
        for (int j = 0; j < 2; j++)
#pragma unroll
            for (int e = 0; e < 4; e++) c_r[mt][j][e] = 0.f;

#pragma unroll 1
    for (int t = 0; t < KNBR; t++) {
        // ---- init acc from gathered projection (fp32, exact) ----
#pragma unroll
        for (int mt = 0; mt < 4; mt++) {
            int r0   = mt * 16 + g4;
            int idx0 = nbs[r0 * KNBR + t];
            int idx1 = nbs[(r0 + 8) * KNBR + t];
            const float* p0 = xproj + (size_t)idx0 * 512;
            const float* p1 = xproj + (size_t)idx1 * 512;
#pragma unroll
            for (int gi = 0; gi < 4; gi++)
#pragma unroll
                for (int j = 0; j < 2; j++) {
                    int col = gi * 128 + w * 16 + j * 8 + t4 * 2;
                    float2 v0 = *(const float2*)(p0 + col);
                    float2 v1 = *(const float2*)(p1 + col);
                    int nt = gi * 2 + j;
                    d[mt][nt][0] = v0.x; d[mt][nt][1] = v0.y;
                    d[mt][nt][2] = v1.x; d[mt][nt][3] = v1.y;
                }
        }

        if (t > 0) {
            // ---- z += h @ Whh^T via tf32 mma ----
#pragma unroll 1
            for (int kc = 0; kc < 128; kc += 16) {
                __syncthreads();
                // stage Whh[:, kc:kc+16] transposed to k-major, tf32 bits
#pragma unroll
                for (int rr = 0; rr < 2; rr++) {
                    int r = tid + rr * 256;                 // n row 0..511
                    const float4* wp = (const float4*)(Whh + (size_t)r * 128 + kc);
#pragma unroll
                    for (int q = 0; q < 4; q++) {
                        float4 v = wp[q];
                        Ws[(q * 4 + 0) * WS_STRIDE + r] = cvt_tf32(v.x);
                        Ws[(q * 4 + 1) * WS_STRIDE + r] = cvt_tf32(v.y);
                        Ws[(q * 4 + 2) * WS_STRIDE + r] = cvt_tf32(v.z);
                        Ws[(q * 4 + 3) * WS_STRIDE + r] = cvt_tf32(v.w);
                    }
                }
                __syncthreads();
#pragma unroll
                for (int kt = 0; kt < 2; kt++) {
                    unsigned a[4][4];
                    int colk = kc + kt * 8 + t4;
#pragma unroll
                    for (int mt = 0; mt < 4; mt++) {
                        int r0 = mt * 16 + g4;
                        a[mt][0] = cvt_tf32(hs[r0 * HS_STRIDE + colk]);
                        a[mt][1] = cvt_tf32(hs[(r0 + 8) * HS_STRIDE + colk]);
                        a[mt][2] = cvt_tf32(hs[r0 * HS_STRIDE + colk + 4]);
                        a[mt][3] = cvt_tf32(hs[(r0 + 8) * HS_STRIDE + colk + 4]);
                    }
                    int kl = kt * 8 + t4;
#pragma unroll
                    for (int nt = 0; nt < 8; nt++) {
                        int gi = nt >> 1, j = nt & 1;
                        int n  = gi * 128 + w * 16 + j * 8 + g4;
                        unsigned b0 = Ws[kl * WS_STRIDE + n];
                        unsigned b1 = Ws[(kl + 4) * WS_STRIDE + n];
#pragma unroll
                        for (int mt = 0; mt < 4; mt++)
                            mma_tf32(d[mt][nt], a[mt], b0, b1);
                    }
                }
            }
            __syncthreads();   // hs reads done before overwrite
        }

        // ---- gates (lane-local across i,f,g,o) + write new h ----
#pragma unroll
        for (int mt = 0; mt < 4; mt++)
#pragma unroll
            for (int j = 0; j < 2; j++)
#pragma unroll
                for (int e = 0; e < 4; e++) {
                    float zi = d[mt][0 + j][e];
                    float zf = d[mt][2 + j][e];
                    float zg = d[mt][4 + j][e];
                    float zo = d[mt][6 + j][e];
                    float i_ = sigf(zi);
                    float f_ = sigf(zf);
                    float g_ = tanh_f(zg);
                    float o_ = sigf(zo);
                    float c  = f_ * c_r[mt][j][e] + i_ * g_;
                    c_r[mt][j][e] = c;
                    float h = o_ * tanh_f(c);
                    int row = mt * 16 + g4 + ((e >> 1) ? 8 : 0);
                    int col = w * 16 + j * 8 + t4 * 2 + (e & 1);
                    hs[row * HS_STRIDE + col] = h;
                }
        __syncthreads();
    }

    // ---- write final hidden state ----
    for (int i = tid; i < 64 * 32; i += 256) {
        int r  = i >> 5;
        int c4 = (i & 31) * 4;
        int nid = base + r;
        if (nid < N_NODES)
            *(float4*)(hout + (size_t)nid * 128 + c4) =
                *(const float4*)(hs + r * HS_STRIDE + c4);
    }
}

// ---------------------------------------------------------------------------
// Kernel 3: y = X @ Wself^T + bself + Hn @ Wneigh^T  (+ BN partials)
// ---------------------------------------------------------------------------
__global__ __launch_bounds__(256) void outproj_kernel(
    const float* __restrict__ X,  const float* __restrict__ Wself,
    const float* __restrict__ bself,
    const float* __restrict__ Hn, const float* __restrict__ Wneigh,
    float* __restrict__ Y, float* __restrict__ psum, float* __restrict__ psq)
{
    __shared__ float As[16 * 128];
    __shared__ float Bs[16 * 128];
    const int tid = threadIdx.x;
    const int tx = tid & 15, ty = tid >> 4;
    const int m0 = blockIdx.x * 128;

    float acc[8][8];
#pragma unroll
    for (int i = 0; i < 8; i++)
#pragma unroll
        for (int j = 0; j < 8; j++) acc[i][j] = 0.f;

#pragma unroll 1
    for (int seg = 0; seg < 2; seg++) {
        const float* Ap = seg ? Hn : X;
        const float* Wp = seg ? Wneigh : Wself;
#pragma unroll 1
        for (int kc = 0; kc < 128; kc += 16) {
            __syncthreads();
#pragma unroll
            for (int q = 0; q < 2; q++) {
                int slot = tid * 2 + q;
                int row  = slot >> 2;
                int k4   = (slot & 3) << 2;
                float4 va = make_float4(0.f, 0.f, 0.f, 0.f);
                int gm = m0 + row;
                if (gm < N_NODES) va = *(const float4*)(Ap + (size_t)gm * 128 + kc + k4);
                As[(k4 + 0) * 128 + row] = va.x;
                As[(k4 + 1) * 128 + row] = va.y;
                As[(k4 + 2) * 128 + row] = va.z;
                As[(k4 + 3) * 128 + row] = va.w;
                float4 vb = *(const float4*)(Wp + (size_t)row * 128 + kc + k4);
                Bs[(k4 + 0) * 128 + row] = vb.x;
                Bs[(k4 + 1) * 128 + row] = vb.y;
                Bs[(k4 + 2) * 128 + row] = vb.z;
                Bs[(k4 + 3) * 128 + row] = vb.w;
            }
            __syncthreads();
#pragma unroll
            for (int k = 0; k < 16; k++) {
                float a[8], b[8];
                *(float4*)&a[0] = *(const float4*)&As[k * 128 + tx * 8];
                *(float4*)&a[4] = *(const float4*)&As[k * 128 + tx * 8 + 4];
                *(float4*)&b[0] = *(const float4*)&Bs[k * 128 + ty * 8];
                *(float4*)&b[4] = *(const float4*)&Bs[k * 128 + ty * 8 + 4];
#pragma unroll
                for (int i = 0; i < 8; i++)
#pragma unroll
                    for (int j = 0; j < 8; j++)
                        acc[i][j] = fmaf(a[i], b[j], acc[i][j]);
            }
        }
    }

    float bias[8];
#pragma unroll
    for (int j = 0; j < 8; j++) bias[j] = bself[ty * 8 + j];

    float cs[8], cq[8];
#pragma unroll
    for (int j = 0; j < 8; j++) { cs[j] = 0.f; cq[j] = 0.f; }

#pragma unroll
    for (int i = 0; i < 8; i++) {
        int gm = m0 + tx * 8 + i;
        if (gm < N_NODES) {
            float v[8];
#pragma unroll
            for (int j = 0; j < 8; j++) v[j] = acc[i][j] + bias[j];
            *(float4*)(Y + (size_t)gm * 128 + ty * 8 + 0) =
                make_float4(v[0], v[1], v[2], v[3]);
            *(float4*)(Y + (size_t)gm * 128 + ty * 8 + 4) =
                make_float4(v[4], v[5], v[6], v[7]);
#pragma unroll
            for (int j = 0; j < 8; j++) { cs[j] += v[j]; cq[j] += v[j] * v[j]; }
        }
    }

    float* red = As;
    __syncthreads();
#pragma unroll
    for (int j = 0; j < 8; j++) red[tx * 128 + ty * 8 + j] = cs[j];
    __syncthreads();
    if (tid < 128) {
        float s = 0.f;
#pragma unroll
        for (int x = 0; x < 16; x++) s += red[x * 128 + tid];
        psum[blockIdx.x * 128 + tid] = s;
    }
    __syncthreads();
#pragma unroll
    for (int j = 0; j < 8; j++) red[tx * 128 + ty * 8 + j] = cq[j];
    __syncthreads();
    if (tid < 128) {
        float s = 0.f;
#pragma unroll
        for (int x = 0; x < 16; x++) s += red[x * 128 + tid];
        psq[blockIdx.x * 128 + tid] = s;
    }
}

// ---------------------------------------------------------------------------
// Kernel 4: BN statistics — one block per channel
// ---------------------------------------------------------------------------
__global__ void bn_reduce(const float* __restrict__ psum,
                          const float* __restrict__ psq,
                          float* __restrict__ stats)
{
    __shared__ float rs[16], rq[16];
    const int c = blockIdx.x;
    const int tid = threadIdx.x;
    float s = 0.f, s2 = 0.f;
    for (int b = tid; b < GM; b += 256) {
        s  += psum[b * 128 + c];
        s2 += psq [b * 128 + c];
    }
#pragma unroll
    for (int o = 16; o > 0; o >>= 1) {
        s  += __shfl_down_sync(0xffffffffu, s,  o);
        s2 += __shfl_down_sync(0xffffffffu, s2, o);
    }
    if ((tid & 31) == 0) { rs[tid >> 5] = s; rq[tid >> 5] = s2; }
    __syncthreads();
    if (tid == 0) {
        float ts = 0.f, tq = 0.f;
#pragma unroll
        for (int i = 0; i < 8; i++) { ts += rs[i]; tq += rq[i]; }
        float mean = ts / (float)N_NODES;
        float var  = tq / (float)N_NODES - mean * mean;
        if (var < 0.f) var = 0.f;
        stats[c]       = mean;
        stats[128 + c] = rsqrtf(var + 1e-5f);
    }
}

// ---------------------------------------------------------------------------
// Kernel 5: BN apply (+ optional ReLU)
// ---------------------------------------------------------------------------
__global__ void bn_apply(const float* __restrict__ X,
                         const float* __restrict__ stats,
                         const float* __restrict__ gamma,
                         const float* __restrict__ beta,
                         float* __restrict__ Y, int relu)
{
    size_t i = (size_t)blockIdx.x * blockDim.x + threadIdx.x;
    if (i * 4 >= (size_t)N_NODES * D) return;
    float4 v = ((const float4*)X)[i];
    int c = (int)((i * 4) & (D - 1));
    float r[4] = {v.x, v.y, v.z, v.w};
#pragma unroll
    for (int e = 0; e < 4; e++) {
        float y = (r[e] - stats[c + e]) * stats[128 + c + e] * gamma[c + e] + beta[c + e];
        if (relu) y = fmaxf(y, 0.f);
        r[e] = y;
    }
    ((float4*)Y)[i] = make_float4(r[0], r[1], r[2], r[3]);
}

// ---------------------------------------------------------------------------
// launch
// ---------------------------------------------------------------------------
extern "C" void kernel_launch(void* const* d_in, const int* in_sizes, int n_in,
                              void* d_out, int out_size)
{
    const float* in_feat = (const float*)d_in[0];
    const int*   nbr     = (const int*)  d_in[1];
    const float* Wih1    = (const float*)d_in[2];
    const float* Whh1    = (const float*)d_in[3];
    const float* bih1    = (const float*)d_in[4];
    const float* bhh1    = (const float*)d_in[5];
    const float* Wself1  = (const float*)d_in[6];
    const float* bself1  = (const float*)d_in[7];
    const float* Wneigh1 = (const float*)d_in[8];
    const float* gamma1  = (const float*)d_in[9];
    const float* beta1   = (const float*)d_in[10];
    const float* Wih2    = (const float*)d_in[11];
    const float* Whh2    = (const float*)d_in[12];
    const float* bih2    = (const float*)d_in[13];
    const float* bhh2    = (const float*)d_in[14];
    const float* Wself2  = (const float*)d_in[15];
    const float* bself2  = (const float*)d_in[16];
    const float* Wneigh2 = (const float*)d_in[17];
    const float* gamma2  = (const float*)d_in[18];
    const float* beta2   = (const float*)d_in[19];
    float* out = (float*)d_out;

    float *xp, *hn, *tmp, *y1, *ps, *pq, *st;
    cudaGetSymbolAddress((void**)&xp,  g_xproj);
    cudaGetSymbolAddress((void**)&hn,  g_hneigh);
    cudaGetSymbolAddress((void**)&tmp, g_tmp);
    cudaGetSymbolAddress((void**)&y1,  g_y1);
    cudaGetSymbolAddress((void**)&ps,  g_psum);
    cudaGetSymbolAddress((void**)&pq,  g_psq);
    cudaGetSymbolAddress((void**)&st,  g_stats);

    cudaFuncSetAttribute(lstm_mma_kernel,
                         cudaFuncAttributeMaxDynamicSharedMemorySize,
                         LSTM_SMEM_BYTES);

    dim3 gproj(GM, 4);
    int bn_blocks = (int)(((size_t)N_NODES * D / 4 + 255) / 256);

    // ---- layer 1 ----
    proj_kernel    <<<gproj, 256>>>(in_feat, Wih1, bih1, bhh1, xp);
    lstm_mma_kernel<<<LBLK, 256, LSTM_SMEM_BYTES>>>(xp, nbr, Whh1, hn);
    outproj_kernel <<<GM, 256>>>(in_feat, Wself1, bself1, hn, Wneigh1, tmp, ps, pq);
    bn_reduce      <<<128, 256>>>(ps, pq, st);
    bn_apply       <<<bn_blocks, 256>>>(tmp, st, gamma1, beta1, y1, 1);

    // ---- layer 2 ----
    proj_kernel    <<<gproj, 256>>>(y1, Wih2, bih2, bhh2, xp);
    lstm_mma_kernel<<<LBLK, 256, LSTM_SMEM_BYTES>>>(xp, nbr, Whh2, hn);
    outproj_kernel <<<GM, 256>>>(y1, Wself2, bself2, hn, Wneigh2, tmp, ps, pq);
    bn_reduce      <<<128, 256>>>(ps, pq, st);
    bn_apply       <<<bn_blocks, 256>>>(tmp, st, gamma2, beta2, out, 0);
}

// round 3
// speedup vs baseline: 3.6635x; 2.0886x over previous
#include <cuda_runtime.h>

// ---------------------------------------------------------------------------
// GraphSAGE (LSTM aggregator) — 2 layers, N=100000, K=16, D=128
//
//   1. proj:     xproj[N,512] = x @ Wih^T + (bih + bhh)          (FFMA GEMM)
//   2. lstm:     per-block (64 nodes) LSTM, 16 steps; Whh lives in SMEM as
//                bf16 for the WHOLE kernel; recurrent h@Whh^T via
//                mma.m16n8k16.bf16; gather + gates + final h in fp32.
//   3. outproj:  y = x @ Wself^T + bself + h_neigh @ Wneigh^T    (+BN partials)
//   4. bn_reduce + bn_apply (+ReLU layer 1)
// ---------------------------------------------------------------------------

#define N_NODES 100000
#define KNBR    16
#define D       128
#define D4      512
#define GM      782              // ceil(N_NODES / 128)
#define LBLK    1563             // ceil(N_NODES / 64)

__device__ float g_xproj [(size_t)N_NODES * D4];
__device__ float g_hneigh[(size_t)N_NODES * D];
__device__ float g_tmp   [(size_t)N_NODES * D];
__device__ float g_y1    [(size_t)N_NODES * D];
__device__ float g_psum  [GM * D];
__device__ float g_psq   [GM * D];
__device__ float g_stats [2 * D];

__device__ __forceinline__ float sigf(float x) {
    return __fdividef(1.0f, 1.0f + __expf(-x));
}
__device__ __forceinline__ float tanh_f(float x) {
    return 2.0f * __fdividef(1.0f, 1.0f + __expf(-2.0f * x)) - 1.0f;
}
// pack two fp32 -> bf16x2 (lo = first arg)
__device__ __forceinline__ unsigned pk_bf16(float lo, float hi) {
    unsigned r;
    asm("cvt.rn.bf16x2.f32 %0, %1, %2;" : "=r"(r) : "f"(hi), "f"(lo));
    return r;
}
__device__ __forceinline__ void mma_bf16(float* d, const unsigned* a,
                                         unsigned b0, unsigned b1) {
    asm volatile(
        "mma.sync.aligned.m16n8k16.row.col.f32.bf16.bf16.f32 "
        "{%0,%1,%2,%3}, {%4,%5,%6,%7}, {%8,%9}, {%0,%1,%2,%3};"
        : "+f"(d[0]), "+f"(d[1]), "+f"(d[2]), "+f"(d[3])
        : "r"(a[0]), "r"(a[1]), "r"(a[2]), "r"(a[3]), "r"(b0), "r"(b1));
}

// ---------------------------------------------------------------------------
// Kernel 1: xproj = A[M,128] @ W[512,128]^T + (b1 + b2)   -> C[M,512]
// ---------------------------------------------------------------------------
__global__ __launch_bounds__(256) void proj_kernel(
    const float* __restrict__ A, const float* __restrict__ W,
    const float* __restrict__ b1, const float* __restrict__ b2,
    float* __restrict__ C)
{
    __shared__ float As[16 * 128];
    __shared__ float Bs[16 * 128];
    const int tid = threadIdx.x;
    const int tx = tid & 15, ty = tid >> 4;
    const int m0 = blockIdx.x * 128;
    const int n0 = blockIdx.y * 128;

    float acc[8][8];
#pragma unroll
    for (int i = 0; i < 8; i++)
#pragma unroll
        for (int j = 0; j < 8; j++) acc[i][j] = 0.f;

#pragma unroll 1
    for (int kc = 0; kc < 128; kc += 16) {
        __syncthreads();
#pragma unroll
        for (int q = 0; q < 2; q++) {
            int slot = tid * 2 + q;
            int row  = slot >> 2;
            int k4   = (slot & 3) << 2;
            float4 va = make_float4(0.f, 0.f, 0.f, 0.f);
            int gm = m0 + row;
            if (gm < N_NODES) va = *(const float4*)(A + (size_t)gm * 128 + kc + k4);
            As[(k4 + 0) * 128 + row] = va.x;
            As[(k4 + 1) * 128 + row] = va.y;
            As[(k4 + 2) * 128 + row] = va.z;
            As[(k4 + 3) * 128 + row] = va.w;
            float4 vb = *(const float4*)(W + (size_t)(n0 + row) * 128 + kc + k4);
            Bs[(k4 + 0) * 128 + row] = vb.x;
            Bs[(k4 + 1) * 128 + row] = vb.y;
            Bs[(k4 + 2) * 128 + row] = vb.z;
            Bs[(k4 + 3) * 128 + row] = vb.w;
        }
        __syncthreads();
#pragma unroll
        for (int k = 0; k < 16; k++) {
            float a[8], b[8];
            *(float4*)&a[0] = *(const float4*)&As[k * 128 + tx * 8];
            *(float4*)&a[4] = *(const float4*)&As[k * 128 + tx * 8 + 4];
            *(float4*)&b[0] = *(const float4*)&Bs[k * 128 + ty * 8];
            *(float4*)&b[4] = *(const float4*)&Bs[k * 128 + ty * 8 + 4];
#pragma unroll
            for (int i = 0; i < 8; i++)
#pragma unroll
                for (int j = 0; j < 8; j++)
                    acc[i][j] = fmaf(a[i], b[j], acc[i][j]);
        }
    }

    float bias[8];
#pragma unroll
    for (int j = 0; j < 8; j++) {
        int n = n0 + ty * 8 + j;
        bias[j] = b1[n] + b2[n];
    }
#pragma unroll
    for (int i = 0; i < 8; i++) {
        int gm = m0 + tx * 8 + i;
        if (gm >= N_NODES) continue;
#pragma unroll
        for (int j4 = 0; j4 < 8; j4 += 4) {
            float4 o;
            o.x = acc[i][j4 + 0] + bias[j4 + 0];
            o.y = acc[i][j4 + 1] + bias[j4 + 1];
            o.z = acc[i][j4 + 2] + bias[j4 + 2];
            o.w = acc[i][j4 + 3] + bias[j4 + 3];
            *(float4*)(C + (size_t)gm * 512 + n0 + ty * 8 + j4) = o;
        }
    }
}

// ---------------------------------------------------------------------------
// Kernel 2: LSTM aggregation, bf16 mma, SMEM-resident Whh.
// Block = 64 nodes, 256 threads (8 warps). Warp w owns columns
// [w*16, w*16+16) of every gate segment. z accumulators in registers
// (C-fragment layout), h stored as packed bf16x2 in SMEM (mma A operand);
// final h written to gmem in fp32 straight from registers.
// SMEM: Wk[64][520] u32 (bf16x2 pairs along k, n-major rows, padded),
//       hb[64][68]  u32 (bf16x2 pairs along k, padded: 4*g4+t4 bank-unique)
// ---------------------------------------------------------------------------
#define WKS 520
#define HBS 68
#define LSTM_SMEM_BYTES ((64 * WKS + 64 * HBS + 64 * KNBR) * 4)

__global__ __launch_bounds__(256) void lstm_bf16_kernel(
    const float* __restrict__ xproj,   // [N,512] biases folded in
    const int*   __restrict__ nbr,     // [N,16]
    const float* __restrict__ Whh,     // [512,128]
    float*       __restrict__ hout)    // [N,128]
{
    extern __shared__ unsigned smu[];
    unsigned* Wk  = smu;                       // [64][520]
    unsigned* hb  = smu + 64 * WKS;            // [64][68]
    int*      nbs = (int*)(smu + 64 * WKS + 64 * HBS);

    const int tid  = threadIdx.x;
    const int w    = tid >> 5;
    const int lane = tid & 31;
    const int g4   = lane >> 2;
    const int t4   = lane & 3;
    const int base = blockIdx.x * 64;

    // neighbors (clamped for tail block)
    for (int i = tid; i < 64 * KNBR; i += 256) {
        int nid = base + (i >> 4);
        if (nid >= N_NODES) nid = N_NODES - 1;
        nbs[i] = nbr[(size_t)nid * KNBR + (i & 15)];
    }

    // stage Whh once: bf16 packed k-major. Wk[kk][n] = {W[n][2kk], W[n][2kk+1]}
#pragma unroll 1
    for (int rr = 0; rr < 2; rr++) {
        int n = tid + rr * 256;
        const float4* wp = (const float4*)(Whh + (size_t)n * 128);
#pragma unroll 8
        for (int q = 0; q < 32; q++) {
            float4 v = wp[q];
            Wk[(2 * q + 0) * WKS + n] = pk_bf16(v.x, v.y);
            Wk[(2 * q + 1) * WKS + n] = pk_bf16(v.z, v.w);
        }
    }
    __syncthreads();

    float d[4][8][4];          // [m-tile][gate*2+j][frag]
    float c_r[4][2][4];
#pragma unroll
    for (int mt = 0; mt < 4; mt++)
#pragma unroll
        for (int j = 0; j < 2; j++)
#pragma unroll
            for (int e = 0; e < 4; e++) c_r[mt][j][e] = 0.f;

#pragma unroll 1
    for (int t = 0; t < KNBR; t++) {
        // ---- init acc from gathered projection (fp32, exact) ----
#pragma unroll
        for (int mt = 0; mt < 4; mt++) {
            int r0   = mt * 16 + g4;
            int idx0 = nbs[r0 * KNBR + t];
            int idx1 = nbs[(r0 + 8) * KNBR + t];
            const float* p0 = xproj + (size_t)idx0 * 512;
            const float* p1 = xproj + (size_t)idx1 * 512;
#pragma unroll
            for (int nt = 0; nt < 8; nt++) {
                int gi = nt >> 1, j = nt & 1;
                int col = gi * 128 + w * 16 + j * 8 + t4 * 2;
                float2 v0 = *(const float2*)(p0 + col);
                float2 v1 = *(const float2*)(p1 + col);
                d[mt][nt][0] = v0.x; d[mt][nt][1] = v0.y;
                d[mt][nt][2] = v1.x; d[mt][nt][3] = v1.y;
            }
        }

        // ---- z += h @ Whh^T (bf16 mma, k = 8 chunks of 16) ----
        if (t > 0) {
#pragma unroll 2
            for (int c = 0; c < 8; c++) {
                const int k0 = c * 8 + t4;
                unsigned a[4][4];
#pragma unroll
                for (int mt = 0; mt < 4; mt++) {
                    int rb = (mt * 16 + g4) * HBS;
                    a[mt][0] = hb[rb + k0];
                    a[mt][1] = hb[rb + 8 * HBS + k0];
                    a[mt][2] = hb[rb + k0 + 4];
                    a[mt][3] = hb[rb + 8 * HBS + k0 + 4];
                }
#pragma unroll
                for (int nt = 0; nt < 8; nt++) {
                    int gi = nt >> 1, j = nt & 1;
                    int n  = gi * 128 + w * 16 + j * 8 + g4;
                    unsigned b0 = Wk[k0 * WKS + n];
                    unsigned b1 = Wk[(k0 + 4) * WKS + n];
#pragma unroll
                    for (int mt = 0; mt < 4; mt++)
                        mma_bf16(d[mt][nt], a[mt], b0, b1);
                }
            }
        }
        __syncthreads();   // mma reads of hb complete before overwrite

        // ---- gates + state update ----
#pragma unroll
        for (int mt = 0; mt < 4; mt++) {
            int r0 = mt * 16 + g4;
#pragma unroll
            for (int j = 0; j < 2; j++) {
                float h[4];
#pragma unroll
                for (int e = 0; e < 4; e++) {
                    float i_ = sigf(d[mt][0 + j][e]);
                    float f_ = sigf(d[mt][2 + j][e]);
                    float g_ = tanh_f(d[mt][4 + j][e]);
                    float o_ = sigf(d[mt][6 + j][e]);
                    float cc = f_ * c_r[mt][j][e] + i_ * g_;
                    c_r[mt][j][e] = cc;
                    h[e] = o_ * tanh_f(cc);
                }
                if (t < KNBR - 1) {
                    int cb = w * 8 + j * 4 + t4;
                    hb[r0 * HBS + cb]       = pk_bf16(h[0], h[1]);
                    hb[(r0 + 8) * HBS + cb] = pk_bf16(h[2], h[3]);
                } else {
                    int col = w * 16 + j * 8 + t4 * 2;
                    int n0 = base + r0, n1 = base + r0 + 8;
                    if (n0 < N_NODES)
                        *(float2*)(hout + (size_t)n0 * 128 + col) =
                            make_float2(h[0], h[1]);
                    if (n1 < N_NODES)
                        *(float2*)(hout + (size_t)n1 * 128 + col) =
                            make_float2(h[2], h[3]);
                }
            }
        }
        if (t < KNBR - 1) __syncthreads();   // hb visible for next step
    }
}

// ---------------------------------------------------------------------------
// Kernel 3: y = X @ Wself^T + bself + Hn @ Wneigh^T  (+ BN partials)
// ---------------------------------------------------------------------------
__global__ __launch_bounds__(256) void outproj_kernel(
    const float* __restrict__ X,  const float* __restrict__ Wself,
    const float* __restrict__ bself,
    const float* __restrict__ Hn, const float* __restrict__ Wneigh,
    float* __restrict__ Y, float* __restrict__ psum, float* __restrict__ psq)
{
    __shared__ float As[16 * 128];
    __shared__ float Bs[16 * 128];
    const int tid = threadIdx.x;
    const int tx = tid & 15, ty = tid >> 4;
    const int m0 = blockIdx.x * 128;

    float acc[8][8];
#pragma unroll
    for (int i = 0; i < 8; i++)
#pragma unroll
        for (int j = 0; j < 8; j++) acc[i][j] = 0.f;

#pragma unroll 1
    for (int seg = 0; seg < 2; seg++) {
        const float* Ap = seg ? Hn : X;
        const float* Wp = seg ? Wneigh : Wself;
#pragma unroll 1
        for (int kc = 0; kc < 128; kc += 16) {
            __syncthreads();
#pragma unroll
            for (int q = 0; q < 2; q++) {
                int slot = tid * 2 + q;
                int row  = slot >> 2;
                int k4   = (slot & 3) << 2;
                float4 va = make_float4(0.f, 0.f, 0.f, 0.f);
                int gm = m0 + row;
                if (gm < N_NODES) va = *(const float4*)(Ap + (size_t)gm * 128 + kc + k4);
                As[(k4 + 0) * 128 + row] = va.x;
                As[(k4 + 1) * 128 + row] = va.y;
                As[(k4 + 2) * 128 + row] = va.z;
                As[(k4 + 3) * 128 + row] = va.w;
                float4 vb = *(const float4*)(Wp + (size_t)row * 128 + kc + k4);
                Bs[(k4 + 0) * 128 + row] = vb.x;
                Bs[(k4 + 1) * 128 + row] = vb.y;
                Bs[(k4 + 2) * 128 + row] = vb.z;
                Bs[(k4 + 3) * 128 + row] = vb.w;
            }
            __syncthreads();
#pragma unroll
            for (int k = 0; k < 16; k++) {
                float a[8], b[8];
                *(float4*)&a[0] = *(const float4*)&As[k * 128 + tx * 8];
                *(float4*)&a[4] = *(const float4*)&As[k * 128 + tx * 8 + 4];
                *(float4*)&b[0] = *(const float4*)&Bs[k * 128 + ty * 8];
                *(float4*)&b[4] = *(const float4*)&Bs[k * 128 + ty * 8 + 4];
#pragma unroll
                for (int i = 0; i < 8; i++)
#pragma unroll
                    for (int j = 0; j < 8; j++)
                        acc[i][j] = fmaf(a[i], b[j], acc[i][j]);
            }
        }
    }

    float bias[8];
#pragma unroll
    for (int j = 0; j < 8; j++) bias[j] = bself[ty * 8 + j];

    float cs[8], cq[8];
#pragma unroll
    for (int j = 0; j < 8; j++) { cs[j] = 0.f; cq[j] = 0.f; }

#pragma unroll
    for (int i = 0; i < 8; i++) {
        int gm = m0 + tx * 8 + i;
        if (gm < N_NODES) {
            float v[8];
#pragma unroll
            for (int j = 0; j < 8; j++) v[j] = acc[i][j] + bias[j];
            *(float4*)(Y + (size_t)gm * 128 + ty * 8 + 0) =
                make_float4(v[0], v[1], v[2], v[3]);
            *(float4*)(Y + (size_t)gm * 128 + ty * 8 + 4) =
                make_float4(v[4], v[5], v[6], v[7]);
#pragma unroll
            for (int j = 0; j < 8; j++) { cs[j] += v[j]; cq[j] += v[j] * v[j]; }
        }
    }

    float* red = As;
    __syncthreads();
#pragma unroll
    for (int j = 0; j < 8; j++) red[tx * 128 + ty * 8 + j] = cs[j];
    __syncthreads();
    if (tid < 128) {
        float s = 0.f;
#pragma unroll
        for (int x = 0; x < 16; x++) s += red[x * 128 + tid];
        psum[blockIdx.x * 128 + tid] = s;
    }
    __syncthreads();
#pragma unroll
    for (int j = 0; j < 8; j++) red[tx * 128 + ty * 8 + j] = cq[j];
    __syncthreads();
    if (tid < 128) {
        float s = 0.f;
#pragma unroll
        for (int x = 0; x < 16; x++) s += red[x * 128 + tid];
        psq[blockIdx.x * 128 + tid] = s;
    }
}

// ---------------------------------------------------------------------------
// Kernel 4: BN statistics — one block per channel
// ---------------------------------------------------------------------------
__global__ void bn_reduce(const float* __restrict__ psum,
                          const float* __restrict__ psq,
                          float* __restrict__ stats)
{
    __shared__ float rs[16], rq[16];
    const int c = blockIdx.x;
    const int tid = threadIdx.x;
    float s = 0.f, s2 = 0.f;
    for (int b = tid; b < GM; b += 256) {
        s  += psum[b * 128 + c];
        s2 += psq [b * 128 + c];
    }
#pragma unroll
    for (int o = 16; o > 0; o >>= 1) {
        s  += __shfl_down_sync(0xffffffffu, s,  o);
        s2 += __shfl_down_sync(0xffffffffu, s2, o);
    }
    if ((tid & 31) == 0) { rs[tid >> 5] = s; rq[tid >> 5] = s2; }
    __syncthreads();
    if (tid == 0) {
        float ts = 0.f, tq = 0.f;
#pragma unroll
        for (int i = 0; i < 8; i++) { ts += rs[i]; tq += rq[i]; }
        float mean = ts / (float)N_NODES;
        float var  = tq / (float)N_NODES - mean * mean;
        if (var < 0.f) var = 0.f;
        stats[c]       = mean;
        stats[128 + c] = rsqrtf(var + 1e-5f);
    }
}

// ---------------------------------------------------------------------------
// Kernel 5: BN apply (+ optional ReLU)
// ---------------------------------------------------------------------------
__global__ void bn_apply(const float* __restrict__ X,
                         const float* __restrict__ stats,
                         const float* __restrict__ gamma,
                         const float* __restrict__ beta,
                         float* __restrict__ Y, int relu)
{
    size_t i = (size_t)blockIdx.x * blockDim.x + threadIdx.x;
    if (i * 4 >= (size_t)N_NODES * D) return;
    float4 v = ((const float4*)X)[i];
    int c = (int)((i * 4) & (D - 1));
    float r[4] = {v.x, v.y, v.z, v.w};
#pragma unroll
    for (int e = 0; e < 4; e++) {
        float y = (r[e] - stats[c + e]) * stats[128 + c + e] * gamma[c + e] + beta[c + e];
        if (relu) y = fmaxf(y, 0.f);
        r[e] = y;
    }
    ((float4*)Y)[i] = make_float4(r[0], r[1], r[2], r[3]);
}

// ---------------------------------------------------------------------------
// launch
// ---------------------------------------------------------------------------
extern "C" void kernel_launch(void* const* d_in, const int* in_sizes, int n_in,
                              void* d_out, int out_size)
{
    const float* in_feat = (const float*)d_in[0];
    const int*   nbr     = (const int*)  d_in[1];
    const float* Wih1    = (const float*)d_in[2];
    const float* Whh1    = (const float*)d_in[3];
    const float* bih1    = (const float*)d_in[4];
    const float* bhh1    = (const float*)d_in[5];
    const float* Wself1  = (const float*)d_in[6];
    const float* bself1  = (const float*)d_in[7];
    const float* Wneigh1 = (const float*)d_in[8];
    const float* gamma1  = (const float*)d_in[9];
    const float* beta1   = (const float*)d_in[10];
    const float* Wih2    = (const float*)d_in[11];
    const float* Whh2    = (const float*)d_in[12];
    const float* bih2    = (const float*)d_in[13];
    const float* bhh2    = (const float*)d_in[14];
    const float* Wself2  = (const float*)d_in[15];
    const float* bself2  = (const float*)d_in[16];
    const float* Wneigh2 = (const float*)d_in[17];
    const float* gamma2  = (const float*)d_in[18];
    const float* beta2   = (const float*)d_in[19];
    float* out = (float*)d_out;

    float *xp, *hn, *tmp, *y1, *ps, *pq, *st;
    cudaGetSymbolAddress((void**)&xp,  g_xproj);
    cudaGetSymbolAddress((void**)&hn,  g_hneigh);
    cudaGetSymbolAddress((void**)&tmp, g_tmp);
    cudaGetSymbolAddress((void**)&y1,  g_y1);
    cudaGetSymbolAddress((void**)&ps,  g_psum);
    cudaGetSymbolAddress((void**)&pq,  g_psq);
    cudaGetSymbolAddress((void**)&st,  g_stats);

    cudaFuncSetAttribute(lstm_bf16_kernel,
                         cudaFuncAttributeMaxDynamicSharedMemorySize,
                         LSTM_SMEM_BYTES);

    dim3 gproj(GM, 4);
    int bn_blocks = (int)(((size_t)N_NODES * D / 4 + 255) / 256);

    // ---- layer 1 ----
    proj_kernel     <<<gproj, 256>>>(in_feat, Wih1, bih1, bhh1, xp);
    lstm_bf16_kernel<<<LBLK, 256, LSTM_SMEM_BYTES>>>(xp, nbr, Whh1, hn);
    outproj_kernel  <<<GM, 256>>>(in_feat, Wself1, bself1, hn, Wneigh1, tmp, ps, pq);
    bn_reduce       <<<128, 256>>>(ps, pq, st);
    bn_apply        <<<bn_blocks, 256>>>(tmp, st, gamma1, beta1, y1, 1);

    // ---- layer 2 ----
    proj_kernel     <<<gproj, 256>>>(y1, Wih2, bih2, bhh2, xp);
    lstm_bf16_kernel<<<LBLK, 256, LSTM_SMEM_BYTES>>>(xp, nbr, Whh2, hn);
    outproj_kernel  <<<GM, 256>>>(y1, Wself2, bself2, hn, Wneigh2, tmp, ps, pq);
    bn_reduce       <<<128, 256>>>(ps, pq, st);
    bn_apply        <<<bn_blocks, 256>>>(tmp, st, gamma2, beta2, out, 0);
}

// round 4
// speedup vs baseline: 4.1408x; 1.1303x over previous
#include <cuda_runtime.h>
#include <cuda_bf16.h>

// ---------------------------------------------------------------------------
// GraphSAGE (LSTM aggregator) — 2 layers, N=100000, K=16, D=128
//
//   1. proj (bf16 mma):  xproj[N,512](bf16) = x @ Wih^T + (bih+bhh)
//   2. lstm (bf16 mma):  per-block (64 nodes), 16 steps; Whh SMEM-resident;
//                        gathers bf16 xproj (L2-resident, 102 MB), fp32 gates
//   3. outproj (f32x2):  y = x @ Wself^T + bself + h_neigh @ Wneigh^T
//   4. bn_reduce + bn_apply (+ReLU layer 1)
// ---------------------------------------------------------------------------

#define N_NODES 100000
#define KNBR    16
#define D       128
#define GM      782              // ceil(N_NODES / 128)
#define LBLK    1563             // ceil(N_NODES / 64)

__device__ unsigned g_xproj [(size_t)N_NODES * 256];   // bf16x2 pairs, 102.4 MB
__device__ float    g_hneigh[(size_t)N_NODES * D];
__device__ float    g_tmp   [(size_t)N_NODES * D];
__device__ float    g_y1    [(size_t)N_NODES * D];
__device__ float    g_psum  [GM * D];
__device__ float    g_psq   [GM * D];
__device__ float    g_stats [2 * D];

__device__ __forceinline__ float sigf(float x) {
    return __fdividef(1.0f, 1.0f + __expf(-x));
}
__device__ __forceinline__ float tanh_f(float x) {
    return 2.0f * __fdividef(1.0f, 1.0f + __expf(-2.0f * x)) - 1.0f;
}
// pack two fp32 -> bf16x2 (lo = first arg)
__device__ __forceinline__ unsigned pk_bf16(float lo, float hi) {
    unsigned r;
    asm("cvt.rn.bf16x2.f32 %0, %1, %2;" : "=r"(r) : "f"(hi), "f"(lo));
    return r;
}
__device__ __forceinline__ float2 bf2f(unsigned u) {
    __nv_bfloat162 b = *reinterpret_cast<__nv_bfloat162*>(&u);
    return __bfloat1622float2(b);
}
__device__ __forceinline__ void mma_bf16(float* d, const unsigned* a,
                                         unsigned b0, unsigned b1) {
    asm volatile(
        "mma.sync.aligned.m16n8k16.row.col.f32.bf16.bf16.f32 "
        "{%0,%1,%2,%3}, {%4,%5,%6,%7}, {%8,%9}, {%0,%1,%2,%3};"
        : "+f"(d[0]), "+f"(d[1]), "+f"(d[2]), "+f"(d[3])
        : "r"(a[0]), "r"(a[1]), "r"(a[2]), "r"(a[3]), "r"(b0), "r"(b1));
}
// f32x2 packed FMA (B300; inline-PTX only)
__device__ __forceinline__ void fma2(unsigned long long &d,
                                     unsigned long long a,
                                     unsigned long long b) {
    asm("fma.rn.f32x2 %0, %1, %2, %0;" : "+l"(d) : "l"(a), "l"(b));
}
__device__ __forceinline__ unsigned long long pack2(float x) {
    unsigned int xi = __float_as_uint(x);
    unsigned long long r;
    asm("mov.b64 %0, {%1, %1};" : "=l"(r) : "r"(xi));
    return r;
}
__device__ __forceinline__ float2 unpack2(unsigned long long v) {
    unsigned int lo, hi;
    asm("mov.b64 {%0, %1}, %2;" : "=r"(lo), "=r"(hi) : "l"(v));
    return make_float2(__uint_as_float(lo), __uint_as_float(hi));
}

// ---------------------------------------------------------------------------
// Kernel 1: proj via bf16 mma.  C[N,512](bf16 pairs) = A @ W^T + (b1+b2).
// Block: 128 m-rows x 128 n-cols; 8 warps, warp w owns n-slice [w*16,w*16+16).
// ---------------------------------------------------------------------------
__global__ __launch_bounds__(256) void proj_bf16_kernel(
    const float* __restrict__ A, const float* __restrict__ W,
    const float* __restrict__ b1, const float* __restrict__ b2,
    unsigned* __restrict__ C)
{
    __shared__ unsigned xa[128 * 68];   // bf16x2, [row][kpair], pad 68
    __shared__ unsigned Wb[64 * 132];   // bf16x2, [kpair][n],  pad 132
    __shared__ float    bsm[128];
    const int tid  = threadIdx.x;
    const int w    = tid >> 5;
    const int lane = tid & 31;
    const int g4   = lane >> 2;
    const int t4   = lane & 3;
    const int m0 = blockIdx.x * 128;
    const int n0 = blockIdx.y * 128;

    for (int i = tid; i < 128 * 32; i += 256) {
        int row = i >> 5, q = i & 31;
        int gm = m0 + row;
        float4 v = make_float4(0.f, 0.f, 0.f, 0.f);
        if (gm < N_NODES) v = *(const float4*)(A + (size_t)gm * 128 + q * 4);
        xa[row * 68 + q * 2]     = pk_bf16(v.x, v.y);
        xa[row * 68 + q * 2 + 1] = pk_bf16(v.z, v.w);
    }
    for (int i = tid; i < 128 * 32; i += 256) {
        int n = i >> 5, q = i & 31;
        float4 v = *(const float4*)(W + (size_t)(n0 + n) * 128 + q * 4);
        Wb[(q * 2)     * 132 + n] = pk_bf16(v.x, v.y);
        Wb[(q * 2 + 1) * 132 + n] = pk_bf16(v.z, v.w);
    }
    if (tid < 128) bsm[tid] = b1[n0 + tid] + b2[n0 + tid];
    __syncthreads();

    float d[8][2][4];
#pragma unroll
    for (int mt = 0; mt < 8; mt++)
#pragma unroll
        for (int nt = 0; nt < 2; nt++)
#pragma unroll
            for (int e = 0; e < 4; e++) d[mt][nt][e] = 0.f;

#pragma unroll
    for (int c = 0; c < 8; c++) {
        const int k0 = c * 8 + t4;
        unsigned a[8][4];
#pragma unroll
        for (int mt = 0; mt < 8; mt++) {
            int rb = (mt * 16 + g4) * 68;
            a[mt][0] = xa[rb + k0];
            a[mt][1] = xa[rb + 8 * 68 + k0];
            a[mt][2] = xa[rb + k0 + 4];
            a[mt][3] = xa[rb + 8 * 68 + k0 + 4];
        }
#pragma unroll
        for (int nt = 0; nt < 2; nt++) {
            int n = w * 16 + nt * 8 + g4;
            unsigned bb0 = Wb[k0 * 132 + n];
            unsigned bb1 = Wb[(k0 + 4) * 132 + n];
#pragma unroll
            for (int mt = 0; mt < 8; mt++)
                mma_bf16(d[mt][nt], a[mt], bb0, bb1);
        }
    }

#pragma unroll
    for (int mt = 0; mt < 8; mt++)
#pragma unroll
        for (int nt = 0; nt < 2; nt++) {
            int col = w * 16 + nt * 8 + t4 * 2;
            float bx = bsm[col], by = bsm[col + 1];
            int cp  = (n0 + col) >> 1;
            int gm0 = m0 + mt * 16 + g4;
            int gm1 = gm0 + 8;
            if (gm0 < N_NODES)
                C[(size_t)gm0 * 256 + cp] =
                    pk_bf16(d[mt][nt][0] + bx, d[mt][nt][1] + by);
            if (gm1 < N_NODES)
                C[(size_t)gm1 * 256 + cp] =
                    pk_bf16(d[mt][nt][2] + bx, d[mt][nt][3] + by);
        }
}

// ---------------------------------------------------------------------------
// Kernel 2: LSTM aggregation, bf16 mma, SMEM-resident Whh, bf16 xproj gather.
// ---------------------------------------------------------------------------
#define WKS 520
#define HBS 68
#define LSTM_SMEM_BYTES ((64 * WKS + 64 * HBS + 64 * KNBR) * 4)

__global__ __launch_bounds__(256) void lstm_bf16_kernel(
    const unsigned* __restrict__ xproj,  // [N,256] bf16x2, biases folded in
    const int*      __restrict__ nbr,    // [N,16]
    const float*    __restrict__ Whh,    // [512,128]
    float*          __restrict__ hout)   // [N,128]
{
    extern __shared__ unsigned smu[];
    unsigned* Wk  = smu;                       // [64 kpairs][520]
    unsigned* hb  = smu + 64 * WKS;            // [64 rows][68]
    int*      nbs = (int*)(smu + 64 * WKS + 64 * HBS);

    const int tid  = threadIdx.x;
    const int w    = tid >> 5;
    const int lane = tid & 31;
    const int g4   = lane >> 2;
    const int t4   = lane & 3;
    const int base = blockIdx.x * 64;

    for (int i = tid; i < 64 * KNBR; i += 256) {
        int nid = base + (i >> 4);
        if (nid >= N_NODES) nid = N_NODES - 1;
        nbs[i] = nbr[(size_t)nid * KNBR + (i & 15)];
    }

    // stage Whh once (bf16 packed k-major)
#pragma unroll 1
    for (int rr = 0; rr < 2; rr++) {
        int n = tid + rr * 256;
        const float4* wp = (const float4*)(Whh + (size_t)n * 128);
#pragma unroll 8
        for (int q = 0; q < 32; q++) {
            float4 v = wp[q];
            Wk[(2 * q + 0) * WKS + n] = pk_bf16(v.x, v.y);
            Wk[(2 * q + 1) * WKS + n] = pk_bf16(v.z, v.w);
        }
    }
    __syncthreads();

    float d[4][8][4];
    float c_r[4][2][4];
#pragma unroll
    for (int mt = 0; mt < 4; mt++)
#pragma unroll
        for (int j = 0; j < 2; j++)
#pragma unroll
            for (int e = 0; e < 4; e++) c_r[mt][j][e] = 0.f;

#pragma unroll 1
    for (int t = 0; t < KNBR; t++) {
        // ---- init acc from gathered bf16 projection ----
#pragma unroll
        for (int mt = 0; mt < 4; mt++) {
            int r0   = mt * 16 + g4;
            int idx0 = nbs[r0 * KNBR + t];
            int idx1 = nbs[(r0 + 8) * KNBR + t];
            const unsigned* p0 = xproj + (size_t)idx0 * 256;
            const unsigned* p1 = xproj + (size_t)idx1 * 256;
#pragma unroll
            for (int nt = 0; nt < 8; nt++) {
                int gi = nt >> 1, j = nt & 1;
                int up = gi * 64 + w * 8 + j * 4 + t4;
                float2 f0 = bf2f(p0[up]);
                float2 f1 = bf2f(p1[up]);
                d[mt][nt][0] = f0.x; d[mt][nt][1] = f0.y;
                d[mt][nt][2] = f1.x; d[mt][nt][3] = f1.y;
            }
        }

        // ---- z += h @ Whh^T (bf16 mma) ----
        if (t > 0) {
#pragma unroll 2
            for (int c = 0; c < 8; c++) {
                const int k0 = c * 8 + t4;
                unsigned a[4][4];
#pragma unroll
                for (int mt = 0; mt < 4; mt++) {
                    int rb = (mt * 16 + g4) * HBS;
                    a[mt][0] = hb[rb + k0];
                    a[mt][1] = hb[rb + 8 * HBS + k0];
                    a[mt][2] = hb[rb + k0 + 4];
                    a[mt][3] = hb[rb + 8 * HBS + k0 + 4];
                }
#pragma unroll
                for (int nt = 0; nt < 8; nt++) {
                    int gi = nt >> 1, j = nt & 1;
                    int n  = gi * 128 + w * 16 + j * 8 + g4;
                    unsigned b0 = Wk[k0 * WKS + n];
                    unsigned b1 = Wk[(k0 + 4) * WKS + n];
#pragma unroll
                    for (int mt = 0; mt < 4; mt++)
                        mma_bf16(d[mt][nt], a[mt], b0, b1);
                }
            }
        }
        __syncthreads();   // mma reads of hb complete before overwrite

        // ---- gates + state update ----
#pragma unroll
        for (int mt = 0; mt < 4; mt++) {
            int r0 = mt * 16 + g4;
#pragma unroll
            for (int j = 0; j < 2; j++) {
                float h[4];
#pragma unroll
                for (int e = 0; e < 4; e++) {
                    float i_ = sigf(d[mt][0 + j][e]);
                    float f_ = sigf(d[mt][2 + j][e]);
                    float g_ = tanh_f(d[mt][4 + j][e]);
                    float o_ = sigf(d[mt][6 + j][e]);
                    float cc = f_ * c_r[mt][j][e] + i_ * g_;
                    c_r[mt][j][e] = cc;
                    h[e] = o_ * tanh_f(cc);
                }
                if (t < KNBR - 1) {
                    int cb = w * 8 + j * 4 + t4;
                    hb[r0 * HBS + cb]       = pk_bf16(h[0], h[1]);
                    hb[(r0 + 8) * HBS + cb] = pk_bf16(h[2], h[3]);
                } else {
                    int col = w * 16 + j * 8 + t4 * 2;
                    int n0 = base + r0, n1 = base + r0 + 8;
                    if (n0 < N_NODES)
                        *(float2*)(hout + (size_t)n0 * 128 + col) =
                            make_float2(h[0], h[1]);
                    if (n1 < N_NODES)
                        *(float2*)(hout + (size_t)n1 * 128 + col) =
                            make_float2(h[2], h[3]);
                }
            }
        }
        if (t < KNBR - 1) __syncthreads();
    }
}

// ---------------------------------------------------------------------------
// Kernel 3: y = X @ Wself^T + bself + Hn @ Wneigh^T (+BN partials), f32x2 FMA
// ---------------------------------------------------------------------------
__global__ __launch_bounds__(256) void outproj_kernel(
    const float* __restrict__ X,  const float* __restrict__ Wself,
    const float* __restrict__ bself,
    const float* __restrict__ Hn, const float* __restrict__ Wneigh,
    float* __restrict__ Y, float* __restrict__ psum, float* __restrict__ psq)
{
    __shared__ float As[16 * 128];
    __shared__ float Bs[16 * 128];
    const int tid = threadIdx.x;
    const int tx = tid & 15, ty = tid >> 4;
    const int m0 = blockIdx.x * 128;

    unsigned long long acc2[8][4];
#pragma unroll
    for (int i = 0; i < 8; i++)
#pragma unroll
        for (int jp = 0; jp < 4; jp++) acc2[i][jp] = 0ull;

#pragma unroll 1
    for (int seg = 0; seg < 2; seg++) {
        const float* Ap = seg ? Hn : X;
        const float* Wp = seg ? Wneigh : Wself;
#pragma unroll 1
        for (int kc = 0; kc < 128; kc += 16) {
            __syncthreads();
#pragma unroll
            for (int q = 0; q < 2; q++) {
                int slot = tid * 2 + q;
                int row  = slot >> 2;
                int k4   = (slot & 3) << 2;
                float4 va = make_float4(0.f, 0.f, 0.f, 0.f);
                int gm = m0 + row;
                if (gm < N_NODES) va = *(const float4*)(Ap + (size_t)gm * 128 + kc + k4);
                As[(k4 + 0) * 128 + row] = va.x;
                As[(k4 + 1) * 128 + row] = va.y;
                As[(k4 + 2) * 128 + row] = va.z;
                As[(k4 + 3) * 128 + row] = va.w;
                float4 vb = *(const float4*)(Wp + (size_t)row * 128 + kc + k4);
                Bs[(k4 + 0) * 128 + row] = vb.x;
                Bs[(k4 + 1) * 128 + row] = vb.y;
                Bs[(k4 + 2) * 128 + row] = vb.z;
                Bs[(k4 + 3) * 128 + row] = vb.w;
            }
            __syncthreads();
#pragma unroll
            for (int k = 0; k < 16; k++) {
                float a[8];
                *(float4*)&a[0] = *(const float4*)&As[k * 128 + tx * 8];
                *(float4*)&a[4] = *(const float4*)&As[k * 128 + tx * 8 + 4];
                unsigned long long bq[4];
#pragma unroll
                for (int jp = 0; jp < 4; jp++)
                    bq[jp] = *(const unsigned long long*)&Bs[k * 128 + ty * 8 + jp * 2];
#pragma unroll
                for (int i = 0; i < 8; i++) {
                    unsigned long long ap = pack2(a[i]);
#pragma unroll
                    for (int jp = 0; jp < 4; jp++)
                        fma2(acc2[i][jp], ap, bq[jp]);
                }
            }
        }
    }

    float bias[8];
#pragma unroll
    for (int j = 0; j < 8; j++) bias[j] = bself[ty * 8 + j];

    float cs[8], cq[8];
#pragma unroll
    for (int j = 0; j < 8; j++) { cs[j] = 0.f; cq[j] = 0.f; }

#pragma unroll
    for (int i = 0; i < 8; i++) {
        int gm = m0 + tx * 8 + i;
        if (gm < N_NODES) {
            float v[8];
#pragma unroll
            for (int jp = 0; jp < 4; jp++) {
                float2 p = unpack2(acc2[i][jp]);
                v[jp * 2]     = p.x + bias[jp * 2];
                v[jp * 2 + 1] = p.y + bias[jp * 2 + 1];
            }
            *(float4*)(Y + (size_t)gm * 128 + ty * 8 + 0) =
                make_float4(v[0], v[1], v[2], v[3]);
            *(float4*)(Y + (size_t)gm * 128 + ty * 8 + 4) =
                make_float4(v[4], v[5], v[6], v[7]);
#pragma unroll
            for (int j = 0; j < 8; j++) { cs[j] += v[j]; cq[j] += v[j] * v[j]; }
        }
    }

    float* red = As;
    __syncthreads();
#pragma unroll
    for (int j = 0; j < 8; j++) red[tx * 128 + ty * 8 + j] = cs[j];
    __syncthreads();
    if (tid < 128) {
        float s = 0.f;
#pragma unroll
        for (int x = 0; x < 16; x++) s += red[x * 128 + tid];
        psum[blockIdx.x * 128 + tid] = s;
    }
    __syncthreads();
#pragma unroll
    for (int j = 0; j < 8; j++) red[tx * 128 + ty * 8 + j] = cq[j];
    __syncthreads();
    if (tid < 128) {
        float s = 0.f;
#pragma unroll
        for (int x = 0; x < 16; x++) s += red[x * 128 + tid];
        psq[blockIdx.x * 128 + tid] = s;
    }
}

// ---------------------------------------------------------------------------
// Kernel 4: BN statistics — one block per channel
// ---------------------------------------------------------------------------
__global__ void bn_reduce(const float* __restrict__ psum,
                          const float* __restrict__ psq,
                          float* __restrict__ stats)
{
    __shared__ float rs[16], rq[16];
    const int c = blockIdx.x;
    const int tid = threadIdx.x;
    float s = 0.f, s2 = 0.f;
    for (int b = tid; b < GM; b += 256) {
        s  += psum[b * 128 + c];
        s2 += psq [b * 128 + c];
    }
#pragma unroll
    for (int o = 16; o > 0; o >>= 1) {
        s  += __shfl_down_sync(0xffffffffu, s,  o);
        s2 += __shfl_down_sync(0xffffffffu, s2, o);
    }
    if ((tid & 31) == 0) { rs[tid >> 5] = s; rq[tid >> 5] = s2; }
    __syncthreads();
    if (tid == 0) {
        float ts = 0.f, tq = 0.f;
#pragma unroll
        for (int i = 0; i < 8; i++) { ts += rs[i]; tq += rq[i]; }
        float mean = ts / (float)N_NODES;
        float var  = tq / (float)N_NODES - mean * mean;
        if (var < 0.f) var = 0.f;
        stats[c]       = mean;
        stats[128 + c] = rsqrtf(var + 1e-5f);
    }
}

// ---------------------------------------------------------------------------
// Kernel 5: BN apply (+ optional ReLU)
// ---------------------------------------------------------------------------
__global__ void bn_apply(const float* __restrict__ X,
                         const float* __restrict__ stats,
                         const float* __restrict__ gamma,
                         const float* __restrict__ beta,
                         float* __restrict__ Y, int relu)
{
    size_t i = (size_t)blockIdx.x * blockDim.x + threadIdx.x;
    if (i * 4 >= (size_t)N_NODES * D) return;
    float4 v = ((const float4*)X)[i];
    int c = (int)((i * 4) & (D - 1));
    float r[4] = {v.x, v.y, v.z, v.w};
#pragma unroll
    for (int e = 0; e < 4; e++) {
        float y = (r[e] - stats[c + e]) * stats[128 + c + e] * gamma[c + e] + beta[c + e];
        if (relu) y = fmaxf(y, 0.f);
        r[e] = y;
    }
    ((float4*)Y)[i] = make_float4(r[0], r[1], r[2], r[3]);
}

// ---------------------------------------------------------------------------
// launch
// ---------------------------------------------------------------------------
extern "C" void kernel_launch(void* const* d_in, const int* in_sizes, int n_in,
                              void* d_out, int out_size)
{
    const float* in_feat = (const float*)d_in[0];
    const int*   nbr     = (const int*)  d_in[1];
    const float* Wih1    = (const float*)d_in[2];
    const float* Whh1    = (const float*)d_in[3];
    const float* bih1    = (const float*)d_in[4];
    const float* bhh1    = (const float*)d_in[5];
    const float* Wself1  = (const float*)d_in[6];
    const float* bself1  = (const float*)d_in[7];
    const float* Wneigh1 = (const float*)d_in[8];
    const float* gamma1  = (const float*)d_in[9];
    const float* beta1   = (const float*)d_in[10];
    const float* Wih2    = (const float*)d_in[11];
    const float* Whh2    = (const float*)d_in[12];
    const float* bih2    = (const float*)d_in[13];
    const float* bhh2    = (const float*)d_in[14];
    const float* Wself2  = (const float*)d_in[15];
    const float* bself2  = (const float*)d_in[16];
    const float* Wneigh2 = (const float*)d_in[17];
    const float* gamma2  = (const float*)d_in[18];
    const float* beta2   = (const float*)d_in[19];
    float* out = (float*)d_out;

    unsigned* xp;
    float *hn, *tmp, *y1, *ps, *pq, *st;
    cudaGetSymbolAddress((void**)&xp,  g_xproj);
    cudaGetSymbolAddress((void**)&hn,  g_hneigh);
    cudaGetSymbolAddress((void**)&tmp, g_tmp);
    cudaGetSymbolAddress((void**)&y1,  g_y1);
    cudaGetSymbolAddress((void**)&ps,  g_psum);
    cudaGetSymbolAddress((void**)&pq,  g_psq);
    cudaGetSymbolAddress((void**)&st,  g_stats);

    cudaFuncSetAttribute(lstm_bf16_kernel,
                         cudaFuncAttributeMaxDynamicSharedMemorySize,
                         LSTM_SMEM_BYTES);

    dim3 gproj(GM, 4);
    int bn_blocks = (int)(((size_t)N_NODES * D / 4 + 255) / 256);

    // ---- layer 1 ----
    proj_bf16_kernel<<<gproj, 256>>>(in_feat, Wih1, bih1, bhh1, xp);
    lstm_bf16_kernel<<<LBLK, 256, LSTM_SMEM_BYTES>>>(xp, nbr, Whh1, hn);
    outproj_kernel  <<<GM, 256>>>(in_feat, Wself1, bself1, hn, Wneigh1, tmp, ps, pq);
    bn_reduce       <<<128, 256>>>(ps, pq, st);
    bn_apply        <<<bn_blocks, 256>>>(tmp, st, gamma1, beta1, y1, 1);

    // ---- layer 2 ----
    proj_bf16_kernel<<<gproj, 256>>>(y1, Wih2, bih2, bhh2, xp);
    lstm_bf16_kernel<<<LBLK, 256, LSTM_SMEM_BYTES>>>(xp, nbr, Whh2, hn);
    outproj_kernel  <<<GM, 256>>>(y1, Wself2, bself2, hn, Wneigh2, tmp, ps, pq);
    bn_reduce       <<<128, 256>>>(ps, pq, st);
    bn_apply        <<<bn_blocks, 256>>>(tmp, st, gamma2, beta2, out, 0);
}

// round 5
// speedup vs baseline: 4.8091x; 1.1614x over previous
#include <cuda_runtime.h>
#include <cuda_fp16.h>

// ---------------------------------------------------------------------------
// GraphSAGE (LSTM aggregator) — 2 layers, N=100000, K=16, D=128
//
//   1. proj (fp16 mma):  xproj[N,512](fp16) = x @ Wih^T + (bih+bhh)
//   2. lstm (fp16 mma):  per-block (64 nodes), 16 steps; Whh SMEM-resident;
//                        gathers fp16 xproj (L2-resident, 102 MB);
//                        gates via MUFU tanh.approx.f32
//   3. outproj (fp16 mma): y = x @ Wself^T + bself + h_neigh @ Wneigh^T
//                          + per-block BN partial sums (warp-shuffle reduce)
//   4. bn_reduce + bn_apply (+ReLU layer 1)
// ---------------------------------------------------------------------------

#define N_NODES 100000
#define KNBR    16
#define D       128
#define GM      782              // ceil(N_NODES / 128)
#define LBLK    1563             // ceil(N_NODES / 64)

__device__ unsigned g_xproj [(size_t)N_NODES * 256];   // fp16x2 pairs, 102.4 MB
__device__ float    g_hneigh[(size_t)N_NODES * D];
__device__ float    g_tmp   [(size_t)N_NODES * D];
__device__ float    g_y1    [(size_t)N_NODES * D];
__device__ float    g_psum  [GM * D];
__device__ float    g_psq   [GM * D];
__device__ float    g_stats [2 * D];

// ---- math helpers ----------------------------------------------------------
__device__ __forceinline__ float tanha(float x) {
    float r;
    asm("tanh.approx.f32 %0, %1;" : "=f"(r) : "f"(x));
    return r;
}
__device__ __forceinline__ float sig_t(float x) {      // sigmoid via tanh
    return fmaf(tanha(0.5f * x), 0.5f, 0.5f);
}
// pack two fp32 -> fp16x2 (lo = first arg)
__device__ __forceinline__ unsigned pk_f16(float lo, float hi) {
    unsigned r;
    asm("cvt.rn.f16x2.f32 %0, %1, %2;" : "=r"(r) : "f"(hi), "f"(lo));
    return r;
}
__device__ __forceinline__ float2 hf2f(unsigned u) {
    __half2 h = *reinterpret_cast<__half2*>(&u);
    return __half22float2(h);
}
__device__ __forceinline__ void mma_f16(float* d, const unsigned* a,
                                        unsigned b0, unsigned b1) {
    asm volatile(
        "mma.sync.aligned.m16n8k16.row.col.f32.f16.f16.f32 "
        "{%0,%1,%2,%3}, {%4,%5,%6,%7}, {%8,%9}, {%0,%1,%2,%3};"
        : "+f"(d[0]), "+f"(d[1]), "+f"(d[2]), "+f"(d[3])
        : "r"(a[0]), "r"(a[1]), "r"(a[2]), "r"(a[3]), "r"(b0), "r"(b1));
}

// ---------------------------------------------------------------------------
// Kernel 1: proj via fp16 mma.  C[N,512](fp16 pairs) = A @ W^T + (b1+b2).
// Block: 128 m-rows x 128 n-cols; 8 warps, warp w owns n-slice [w*16,w*16+16).
// ---------------------------------------------------------------------------
__global__ __launch_bounds__(256) void proj_f16_kernel(
    const float* __restrict__ A, const float* __restrict__ W,
    const float* __restrict__ b1, const float* __restrict__ b2,
    unsigned* __restrict__ C)
{
    __shared__ unsigned xa[128 * 68];   // fp16x2, [row][kpair], pad 68
    __shared__ unsigned Wb[64 * 132];   // fp16x2, [kpair][n],  pad 132
    __shared__ float    bsm[128];
    const int tid  = threadIdx.x;
    const int w    = tid >> 5;
    const int lane = tid & 31;
    const int g4   = lane >> 2;
    const int t4   = lane & 3;
    const int m0 = blockIdx.x * 128;
    const int n0 = blockIdx.y * 128;

    for (int i = tid; i < 128 * 32; i += 256) {
        int row = i >> 5, q = i & 31;
        int gm = m0 + row;
        float4 v = make_float4(0.f, 0.f, 0.f, 0.f);
        if (gm < N_NODES) v = *(const float4*)(A + (size_t)gm * 128 + q * 4);
        xa[row * 68 + q * 2]     = pk_f16(v.x, v.y);
        xa[row * 68 + q * 2 + 1] = pk_f16(v.z, v.w);
    }
    for (int i = tid; i < 128 * 32; i += 256) {
        int n = i >> 5, q = i & 31;
        float4 v = *(const float4*)(W + (size_t)(n0 + n) * 128 + q * 4);
        Wb[(q * 2)     * 132 + n] = pk_f16(v.x, v.y);
        Wb[(q * 2 + 1) * 132 + n] = pk_f16(v.z, v.w);
    }
    if (tid < 128) bsm[tid] = b1[n0 + tid] + b2[n0 + tid];
    __syncthreads();

    float d[8][2][4];
#pragma unroll
    for (int mt = 0; mt < 8; mt++)
#pragma unroll
        for (int nt = 0; nt < 2; nt++)
#pragma unroll
            for (int e = 0; e < 4; e++) d[mt][nt][e] = 0.f;

#pragma unroll
    for (int c = 0; c < 8; c++) {
        const int k0 = c * 8 + t4;
        unsigned a[8][4];
#pragma unroll
        for (int mt = 0; mt < 8; mt++) {
            int rb = (mt * 16 + g4) * 68;
            a[mt][0] = xa[rb + k0];
            a[mt][1] = xa[rb + 8 * 68 + k0];
            a[mt][2] = xa[rb + k0 + 4];
            a[mt][3] = xa[rb + 8 * 68 + k0 + 4];
        }
#pragma unroll
        for (int nt = 0; nt < 2; nt++) {
            int n = w * 16 + nt * 8 + g4;
            unsigned bb0 = Wb[k0 * 132 + n];
            unsigned bb1 = Wb[(k0 + 4) * 132 + n];
#pragma unroll
            for (int mt = 0; mt < 8; mt++)
                mma_f16(d[mt][nt], a[mt], bb0, bb1);
        }
    }

#pragma unroll
    for (int mt = 0; mt < 8; mt++)
#pragma unroll
        for (int nt = 0; nt < 2; nt++) {
            int col = w * 16 + nt * 8 + t4 * 2;
            float bx = bsm[col], by = bsm[col + 1];
            int cp  = (n0 + col) >> 1;
            int gm0 = m0 + mt * 16 + g4;
            int gm1 = gm0 + 8;
            if (gm0 < N_NODES)
                C[(size_t)gm0 * 256 + cp] =
                    pk_f16(d[mt][nt][0] + bx, d[mt][nt][1] + by);
            if (gm1 < N_NODES)
                C[(size_t)gm1 * 256 + cp] =
                    pk_f16(d[mt][nt][2] + bx, d[mt][nt][3] + by);
        }
}

// ---------------------------------------------------------------------------
// Kernel 2: LSTM aggregation, fp16 mma, SMEM-resident Whh, fp16 xproj gather.
// ---------------------------------------------------------------------------
#define WKS 520
#define HBS 68
#define LSTM_SMEM_BYTES ((64 * WKS + 64 * HBS + 64 * KNBR) * 4)

__global__ __launch_bounds__(256) void lstm_f16_kernel(
    const unsigned* __restrict__ xproj,  // [N,256] fp16x2, biases folded in
    const int*      __restrict__ nbr,    // [N,16]
    const float*    __restrict__ Whh,    // [512,128]
    float*          __restrict__ hout)   // [N,128]
{
    extern __shared__ unsigned smu[];
    unsigned* Wk  = smu;                       // [64 kpairs][520]
    unsigned* hb  = smu + 64 * WKS;            // [64 rows][68]
    int*      nbs = (int*)(smu + 64 * WKS + 64 * HBS);

    const int tid  = threadIdx.x;
    const int w    = tid >> 5;
    const int lane = tid & 31;
    const int g4   = lane >> 2;
    const int t4   = lane & 3;
    const int base = blockIdx.x * 64;

    for (int i = tid; i < 64 * KNBR; i += 256) {
        int nid = base + (i >> 4);
        if (nid >= N_NODES) nid = N_NODES - 1;
        nbs[i] = nbr[(size_t)nid * KNBR + (i & 15)];
    }

    // stage Whh once (fp16 packed k-major)
#pragma unroll 1
    for (int rr = 0; rr < 2; rr++) {
        int n = tid + rr * 256;
        const float4* wp = (const float4*)(Whh + (size_t)n * 128);
#pragma unroll 8
        for (int q = 0; q < 32; q++) {
            float4 v = wp[q];
            Wk[(2 * q + 0) * WKS + n] = pk_f16(v.x, v.y);
            Wk[(2 * q + 1) * WKS + n] = pk_f16(v.z, v.w);
        }
    }
    __syncthreads();

    float d[4][8][4];
    float c_r[4][2][4];
#pragma unroll
    for (int mt = 0; mt < 4; mt++)
#pragma unroll
        for (int j = 0; j < 2; j++)
#pragma unroll
            for (int e = 0; e < 4; e++) c_r[mt][j][e] = 0.f;

#pragma unroll 1
    for (int t = 0; t < KNBR; t++) {
        // ---- init acc from gathered fp16 projection ----
#pragma unroll
        for (int mt = 0; mt < 4; mt++) {
            int r0   = mt * 16 + g4;
            int idx0 = nbs[r0 * KNBR + t];
            int idx1 = nbs[(r0 + 8) * KNBR + t];
            const unsigned* p0 = xproj + (size_t)idx0 * 256;
            const unsigned* p1 = xproj + (size_t)idx1 * 256;
#pragma unroll
            for (int nt = 0; nt < 8; nt++) {
                int gi = nt >> 1, j = nt & 1;
                int up = gi * 64 + w * 8 + j * 4 + t4;
                float2 f0 = hf2f(p0[up]);
                float2 f1 = hf2f(p1[up]);
                d[mt][nt][0] = f0.x; d[mt][nt][1] = f0.y;
                d[mt][nt][2] = f1.x; d[mt][nt][3] = f1.y;
            }
        }

        // ---- z += h @ Whh^T (fp16 mma) ----
        if (t > 0) {
#pragma unroll 2
            for (int c = 0; c < 8; c++) {
                const int k0 = c * 8 + t4;
                unsigned a[4][4];
#pragma unroll
                for (int mt = 0; mt < 4; mt++) {
                    int rb = (mt * 16 + g4) * HBS;
                    a[mt][0] = hb[rb + k0];
                    a[mt][1] = hb[rb + 8 * HBS + k0];
                    a[mt][2] = hb[rb + k0 + 4];
                    a[mt][3] = hb[rb + 8 * HBS + k0 + 4];
                }
#pragma unroll
                for (int nt = 0; nt < 8; nt++) {
                    int gi = nt >> 1, j = nt & 1;
                    int n  = gi * 128 + w * 16 + j * 8 + g4;
                    unsigned b0 = Wk[k0 * WKS + n];
                    unsigned b1 = Wk[(k0 + 4) * WKS + n];
#pragma unroll
                    for (int mt = 0; mt < 4; mt++)
                        mma_f16(d[mt][nt], a[mt], b0, b1);
                }
            }
        }
        __syncthreads();   // mma reads of hb complete before overwrite

        // ---- gates (MUFU tanh) + state update ----
#pragma unroll
        for (int mt = 0; mt < 4; mt++) {
            int r0 = mt * 16 + g4;
#pragma unroll
            for (int j = 0; j < 2; j++) {
                float h[4];
#pragma unroll
                for (int e = 0; e < 4; e++) {
                    float i_ = sig_t(d[mt][0 + j][e]);
                    float f_ = sig_t(d[mt][2 + j][e]);
                    float g_ = tanha(d[mt][4 + j][e]);
                    float o_ = sig_t(d[mt][6 + j][e]);
                    float cc = f_ * c_r[mt][j][e] + i_ * g_;
                    c_r[mt][j][e] = cc;
                    h[e] = o_ * tanha(cc);
                }
                if (t < KNBR - 1) {
                    int cb = w * 8 + j * 4 + t4;
                    hb[r0 * HBS + cb]       = pk_f16(h[0], h[1]);
                    hb[(r0 + 8) * HBS + cb] = pk_f16(h[2], h[3]);
                } else {
                    int col = w * 16 + j * 8 + t4 * 2;
                    int n0 = base + r0, n1 = base + r0 + 8;
                    if (n0 < N_NODES)
                        *(float2*)(hout + (size_t)n0 * 128 + col) =
                            make_float2(h[0], h[1]);
                    if (n1 < N_NODES)
                        *(float2*)(hout + (size_t)n1 * 128 + col) =
                            make_float2(h[2], h[3]);
                }
            }
        }
        if (t < KNBR - 1) __syncthreads();
    }
}

// ---------------------------------------------------------------------------
// Kernel 3: outproj via fp16 mma.  Y[N,128](fp32) = X @ Wself^T + bself
//           + Hn @ Wneigh^T.  BN partial sums via xor-shuffle over g4.
// ---------------------------------------------------------------------------
__global__ __launch_bounds__(256) void outproj_f16_kernel(
    const float* __restrict__ X,  const float* __restrict__ Wself,
    const float* __restrict__ bself,
    const float* __restrict__ Hn, const float* __restrict__ Wneigh,
    float* __restrict__ Y, float* __restrict__ psum, float* __restrict__ psq)
{
    __shared__ unsigned xa[128 * 68];
    __shared__ unsigned Wb[64 * 132];
    __shared__ float    bsm[128];
    const int tid  = threadIdx.x;
    const int w    = tid >> 5;
    const int lane = tid & 31;
    const int g4   = lane >> 2;
    const int t4   = lane & 3;
    const int m0 = blockIdx.x * 128;

    if (tid < 128) bsm[tid] = bself[tid];

    float d[8][2][4];
#pragma unroll
    for (int mt = 0; mt < 8; mt++)
#pragma unroll
        for (int nt = 0; nt < 2; nt++)
#pragma unroll
            for (int e = 0; e < 4; e++) d[mt][nt][e] = 0.f;

#pragma unroll 1
    for (int seg = 0; seg < 2; seg++) {
        const float* Ap = seg ? Hn : X;
        const float* Wp = seg ? Wneigh : Wself;
        if (seg) __syncthreads();         // protect previous-iteration reads
        for (int i = tid; i < 128 * 32; i += 256) {
            int row = i >> 5, q = i & 31;
            int gm = m0 + row;
            float4 v = make_float4(0.f, 0.f, 0.f, 0.f);
            if (gm < N_NODES) v = *(const float4*)(Ap + (size_t)gm * 128 + q * 4);
            xa[row * 68 + q * 2]     = pk_f16(v.x, v.y);
            xa[row * 68 + q * 2 + 1] = pk_f16(v.z, v.w);
        }
        for (int i = tid; i < 128 * 32; i += 256) {
            int n = i >> 5, q = i & 31;
            float4 v = *(const float4*)(Wp + (size_t)n * 128 + q * 4);
            Wb[(q * 2)     * 132 + n] = pk_f16(v.x, v.y);
            Wb[(q * 2 + 1) * 132 + n] = pk_f16(v.z, v.w);
        }
        __syncthreads();
#pragma unroll
        for (int c = 0; c < 8; c++) {
            const int k0 = c * 8 + t4;
            unsigned a[8][4];
#pragma unroll
            for (int mt = 0; mt < 8; mt++) {
                int rb = (mt * 16 + g4) * 68;
                a[mt][0] = xa[rb + k0];
                a[mt][1] = xa[rb + 8 * 68 + k0];
                a[mt][2] = xa[rb + k0 + 4];
                a[mt][3] = xa[rb + 8 * 68 + k0 + 4];
            }
#pragma unroll
            for (int nt = 0; nt < 2; nt++) {
                int n = w * 16 + nt * 8 + g4;
                unsigned bb0 = Wb[k0 * 132 + n];
                unsigned bb1 = Wb[(k0 + 4) * 132 + n];
#pragma unroll
                for (int mt = 0; mt < 8; mt++)
                    mma_f16(d[mt][nt], a[mt], bb0, bb1);
            }
        }
    }

    // ---- epilogue: bias add, store fp32 Y, BN partials ----
    float cs[2][2], cq[2][2];
#pragma unroll
    for (int nt = 0; nt < 2; nt++)
#pragma unroll
        for (int e = 0; e < 2; e++) { cs[nt][e] = 0.f; cq[nt][e] = 0.f; }

#pragma unroll
    for (int nt = 0; nt < 2; nt++) {
        int col = w * 16 + nt * 8 + t4 * 2;
        float bx = bsm[col], by = bsm[col + 1];
#pragma unroll
        for (int mt = 0; mt < 8; mt++) {
            int gm0 = m0 + mt * 16 + g4;
            int gm1 = gm0 + 8;
            if (gm0 < N_NODES) {
                float v0 = d[mt][nt][0] + bx;
                float v1 = d[mt][nt][1] + by;
                *(float2*)(Y + (size_t)gm0 * 128 + col) = make_float2(v0, v1);
                cs[nt][0] += v0; cq[nt][0] += v0 * v0;
                cs[nt][1] += v1; cq[nt][1] += v1 * v1;
            }
            if (gm1 < N_NODES) {
                float v0 = d[mt][nt][2] + bx;
                float v1 = d[mt][nt][3] + by;
                *(float2*)(Y + (size_t)gm1 * 128 + col) = make_float2(v0, v1);
                cs[nt][0] += v0; cq[nt][0] += v0 * v0;
                cs[nt][1] += v1; cq[nt][1] += v1 * v1;
            }
        }
    }
    // reduce over the 8 g4 groups (lanes differing in bits 2..4)
#pragma unroll
    for (int o = 4; o <= 16; o <<= 1) {
#pragma unroll
        for (int nt = 0; nt < 2; nt++)
#pragma unroll
            for (int e = 0; e < 2; e++) {
                cs[nt][e] += __shfl_xor_sync(0xffffffffu, cs[nt][e], o);
                cq[nt][e] += __shfl_xor_sync(0xffffffffu, cq[nt][e], o);
            }
    }
    if (g4 == 0) {
#pragma unroll
        for (int nt = 0; nt < 2; nt++) {
            int col = w * 16 + nt * 8 + t4 * 2;
            *(float2*)(psum + blockIdx.x * 128 + col) =
                make_float2(cs[nt][0], cs[nt][1]);
            *(float2*)(psq + blockIdx.x * 128 + col) =
                make_float2(cq[nt][0], cq[nt][1]);
        }
    }
}

// ---------------------------------------------------------------------------
// Kernel 4: BN statistics — one block per channel
// ---------------------------------------------------------------------------
__global__ void bn_reduce(const float* __restrict__ psum,
                          const float* __restrict__ psq,
                          float* __restrict__ stats)
{
    __shared__ float rs[16], rq[16];
    const int c = blockIdx.x;
    const int tid = threadIdx.x;
    float s = 0.f, s2 = 0.f;
    for (int b = tid; b < GM; b += 256) {
        s  += psum[b * 128 + c];
        s2 += psq [b * 128 + c];
    }
#pragma unroll
    for (int o = 16; o > 0; o >>= 1) {
        s  += __shfl_down_sync(0xffffffffu, s,  o);
        s2 += __shfl_down_sync(0xffffffffu, s2, o);
    }
    if ((tid & 31) == 0) { rs[tid >> 5] = s; rq[tid >> 5] = s2; }
    __syncthreads();
    if (tid == 0) {
        float ts = 0.f, tq = 0.f;
#pragma unroll
        for (int i = 0; i < 8; i++) { ts += rs[i]; tq += rq[i]; }
        float mean = ts / (float)N_NODES;
        float var  = tq / (float)N_NODES - mean * mean;
        if (var < 0.f) var = 0.f;
        stats[c]       = mean;
        stats[128 + c] = rsqrtf(var + 1e-5f);
    }
}

// ---------------------------------------------------------------------------
// Kernel 5: BN apply (+ optional ReLU)
// ---------------------------------------------------------------------------
__global__ void bn_apply(const float* __restrict__ X,
                         const float* __restrict__ stats,
                         const float* __restrict__ gamma,
                         const float* __restrict__ beta,
                         float* __restrict__ Y, int relu)
{
    size_t i = (size_t)blockIdx.x * blockDim.x + threadIdx.x;
    if (i * 4 >= (size_t)N_NODES * D) return;
    float4 v = ((const float4*)X)[i];
    int c = (int)((i * 4) & (D - 1));
    float r[4] = {v.x, v.y, v.z, v.w};
#pragma unroll
    for (int e = 0; e < 4; e++) {
        float y = (r[e] - stats[c + e]) * stats[128 + c + e] * gamma[c + e] + beta[c + e];
        if (relu) y = fmaxf(y, 0.f);
        r[e] = y;
    }
    ((float4*)Y)[i] = make_float4(r[0], r[1], r[2], r[3]);
}

// ---------------------------------------------------------------------------
// launch
// ---------------------------------------------------------------------------
extern "C" void kernel_launch(void* const* d_in, const int* in_sizes, int n_in,
                              void* d_out, int out_size)
{
    const float* in_feat = (const float*)d_in[0];
    const int*   nbr     = (const int*)  d_in[1];
    const float* Wih1    = (const float*)d_in[2];
    const float* Whh1    = (const float*)d_in[3];
    const float* bih1    = (const float*)d_in[4];
    const float* bhh1    = (const float*)d_in[5];
    const float* Wself1  = (const float*)d_in[6];
    const float* bself1  = (const float*)d_in[7];
    const float* Wneigh1 = (const float*)d_in[8];
    const float* gamma1  = (const float*)d_in[9];
    const float* beta1   = (const float*)d_in[10];
    const float* Wih2    = (const float*)d_in[11];
    const float* Whh2    = (const float*)d_in[12];
    const float* bih2    = (const float*)d_in[13];
    const float* bhh2    = (const float*)d_in[14];
    const float* Wself2  = (const float*)d_in[15];
    const float* bself2  = (const float*)d_in[16];
    const float* Wneigh2 = (const float*)d_in[17];
    const float* gamma2  = (const float*)d_in[18];
    const float* beta2   = (const float*)d_in[19];
    float* out = (float*)d_out;

    unsigned* xp;
    float *hn, *tmp, *y1, *ps, *pq, *st;
    cudaGetSymbolAddress((void**)&xp,  g_xproj);
    cudaGetSymbolAddress((void**)&hn,  g_hneigh);
    cudaGetSymbolAddress((void**)&tmp, g_tmp);
    cudaGetSymbolAddress((void**)&y1,  g_y1);
    cudaGetSymbolAddress((void**)&ps,  g_psum);
    cudaGetSymbolAddress((void**)&pq,  g_psq);
    cudaGetSymbolAddress((void**)&st,  g_stats);

    cudaFuncSetAttribute(lstm_f16_kernel,
                         cudaFuncAttributeMaxDynamicSharedMemorySize,
                         LSTM_SMEM_BYTES);

    dim3 gproj(GM, 4);
    int bn_blocks = (int)(((size_t)N_NODES * D / 4 + 255) / 256);

    // ---- layer 1 ----
    proj_f16_kernel   <<<gproj, 256>>>(in_feat, Wih1, bih1, bhh1, xp);
    lstm_f16_kernel   <<<LBLK, 256, LSTM_SMEM_BYTES>>>(xp, nbr, Whh1, hn);
    outproj_f16_kernel<<<GM, 256>>>(in_feat, Wself1, bself1, hn, Wneigh1, tmp, ps, pq);
    bn_reduce         <<<128, 256>>>(ps, pq, st);
    bn_apply          <<<bn_blocks, 256>>>(tmp, st, gamma1, beta1, y1, 1);

    // ---- layer 2 ----
    proj_f16_kernel   <<<gproj, 256>>>(y1, Wih2, bih2, bhh2, xp);
    lstm_f16_kernel   <<<LBLK, 256, LSTM_SMEM_BYTES>>>(xp, nbr, Whh2, hn);
    outproj_f16_kernel<<<GM, 256>>>(y1, Wself2, bself2, hn, Wneigh2, tmp, ps, pq);
    bn_reduce         <<<128, 256>>>(ps, pq, st);
    bn_apply          <<<bn_blocks, 256>>>(tmp, st, gamma2, beta2, out, 0);
}